// round 1
// baseline (speedup 1.0000x reference)
#include <cuda_runtime.h>
#include <cuda_bf16.h>

#define S_LEN 2048
#define HIDDEN 3584
#define N_HEADS 28
#define N_KV 4
#define HEAD_DIM 128
#define GROUPS 7
#define QKV_N (N_HEADS * HEAD_DIM + 2 * N_KV * HEAD_DIM)   // 4608
#define ATTN_SCALE 0.08838834764831845f                     // 128^-0.5

// ---------------- scratch (device globals: no allocation allowed) ----------
__device__ float g_q[N_HEADS * S_LEN * HEAD_DIM];   // [h][s][d]
__device__ float g_k[N_KV * S_LEN * HEAD_DIM];
__device__ float g_v[N_KV * S_LEN * HEAD_DIM];
__device__ float g_attn[S_LEN * N_HEADS * HEAD_DIM]; // [s][h*128+d]

// ---------------- 128x128x16 fp32 tile core --------------------------------
// A: [M,K] row-major, rows m0..m0+127. B: [128,K] row-major (weight slice).
// As/Bs stored transposed with stride 132 (conflict padding).
__device__ __forceinline__ void gemm_tile_core(
    const float* __restrict__ A, const float* __restrict__ B,
    int K, int m0, float acc[8][8], float* As, float* Bs)
{
    const int tid = threadIdx.x;
    const int tx = tid & 15;
    const int ty = tid >> 4;

    for (int kb = 0; kb < K; kb += 16) {
        // load A tile (128 rows x 16 cols), transposed into As[k][m]
        #pragma unroll
        for (int p = 0; p < 2; ++p) {
            int idx = tid + p * 256;          // 0..511 float4s
            int row = idx >> 2;
            int c4  = (idx & 3) << 2;         // k offset 0,4,8,12
            float4 v = *reinterpret_cast<const float4*>(A + (long)(m0 + row) * K + kb + c4);
            As[(c4 + 0) * 132 + row] = v.x;
            As[(c4 + 1) * 132 + row] = v.y;
            As[(c4 + 2) * 132 + row] = v.z;
            As[(c4 + 3) * 132 + row] = v.w;
        }
        // load B tile
        #pragma unroll
        for (int p = 0; p < 2; ++p) {
            int idx = tid + p * 256;
            int row = idx >> 2;
            int c4  = (idx & 3) << 2;
            float4 v = *reinterpret_cast<const float4*>(B + (long)row * K + kb + c4);
            Bs[(c4 + 0) * 132 + row] = v.x;
            Bs[(c4 + 1) * 132 + row] = v.y;
            Bs[(c4 + 2) * 132 + row] = v.z;
            Bs[(c4 + 3) * 132 + row] = v.w;
        }
        __syncthreads();

        #pragma unroll
        for (int kk = 0; kk < 16; ++kk) {
            float4 a0 = *reinterpret_cast<float4*>(As + kk * 132 + ty * 8);
            float4 a1 = *reinterpret_cast<float4*>(As + kk * 132 + ty * 8 + 4);
            float4 b0 = *reinterpret_cast<float4*>(Bs + kk * 132 + tx * 8);
            float4 b1 = *reinterpret_cast<float4*>(Bs + kk * 132 + tx * 8 + 4);
            float a[8] = {a0.x, a0.y, a0.z, a0.w, a1.x, a1.y, a1.z, a1.w};
            float b[8] = {b0.x, b0.y, b0.z, b0.w, b1.x, b1.y, b1.z, b1.w};
            #pragma unroll
            for (int i = 0; i < 8; ++i)
                #pragma unroll
                for (int j = 0; j < 8; ++j)
                    acc[i][j] += a[i] * b[j];
        }
        __syncthreads();
    }
}

// ---------------- QKV projection (fused, bias, split outputs) --------------
__global__ __launch_bounds__(256, 2)
void qkv_gemm_kernel(const float* __restrict__ X,
                     const float* __restrict__ Wq, const float* __restrict__ Wk,
                     const float* __restrict__ Wv,
                     const float* __restrict__ bq, const float* __restrict__ bk,
                     const float* __restrict__ bv)
{
    __shared__ float As[16 * 132];
    __shared__ float Bs[16 * 132];

    const int m0 = blockIdx.x * 128;
    const int n0 = blockIdx.y * 128;

    const float* W;
    const float* bias;
    float* dst;
    int head_local;
    if (n0 < N_HEADS * HEAD_DIM) {
        W = Wq + (long)n0 * HIDDEN; bias = bq + n0; dst = g_q; head_local = n0 >> 7;
    } else if (n0 < (N_HEADS + N_KV) * HEAD_DIM) {
        int o = n0 - N_HEADS * HEAD_DIM;
        W = Wk + (long)o * HIDDEN; bias = bk + o; dst = g_k; head_local = o >> 7;
    } else {
        int o = n0 - (N_HEADS + N_KV) * HEAD_DIM;
        W = Wv + (long)o * HIDDEN; bias = bv + o; dst = g_v; head_local = o >> 7;
    }

    float acc[8][8];
    #pragma unroll
    for (int i = 0; i < 8; ++i)
        #pragma unroll
        for (int j = 0; j < 8; ++j) acc[i][j] = 0.f;

    gemm_tile_core(X, W, HIDDEN, m0, acc, As, Bs);

    const int tx = threadIdx.x & 15;
    const int ty = threadIdx.x >> 4;
    float* base = dst + (long)head_local * S_LEN * HEAD_DIM;
    #pragma unroll
    for (int i = 0; i < 8; ++i) {
        int m = m0 + ty * 8 + i;
        #pragma unroll
        for (int j = 0; j < 8; ++j) {
            int dcol = tx * 8 + j;
            base[(long)m * HEAD_DIM + dcol] = acc[i][j] + bias[dcol];
        }
    }
}

// ---------------- RoPE (in place on g_q, g_k) ------------------------------
__global__ void rope_kernel(const float* __restrict__ cos_t,
                            const float* __restrict__ sin_t)
{
    int idx = blockIdx.x * blockDim.x + threadIdx.x;   // (N_HEADS+N_KV)*S*64
    if (idx >= (N_HEADS + N_KV) * S_LEN * 64) return;
    int d = idx & 63;
    int s = (idx >> 6) & (S_LEN - 1);
    int head = idx >> 17;
    float* p = (head < N_HEADS) ? (g_q + (long)head * S_LEN * HEAD_DIM)
                                : (g_k + (long)(head - N_HEADS) * S_LEN * HEAD_DIM);
    float c  = cos_t[s * HEAD_DIM + d];
    float sn = sin_t[s * HEAD_DIM + d];
    float x1 = p[(long)s * HEAD_DIM + d];
    float x2 = p[(long)s * HEAD_DIM + d + 64];
    p[(long)s * HEAD_DIM + d]      = x1 * c - x2 * sn;
    p[(long)s * HEAD_DIM + d + 64] = x2 * c + x1 * sn;
}

// ---------------- flash attention (causal, GQA) -----------------------------
// block: 256 threads, 64 q rows (4 threads per row), 32-key tiles.
// smem layout (floats): Qs[64*132] Ks[32*132] Vs[32*132] Ps[64*36]
#define FLASH_SMEM_FLOATS (64 * 132 + 32 * 132 + 32 * 132 + 64 * 36)

__global__ __launch_bounds__(256, 2)
void flash_kernel()
{
    extern __shared__ float sm[];
    float* Qs = sm;
    float* Ks = Qs + 64 * 132;
    float* Vs = Ks + 32 * 132;
    float* Ps = Vs + 32 * 132;

    const int qb = blockIdx.x;           // 0..31
    const int h  = blockIdx.y;           // 0..27
    const int kv = h / GROUPS;
    const int tid = threadIdx.x;
    const int r = tid >> 2;              // q row within tile, 0..63
    const int t = tid & 3;               // quarter of head dim / key slice

    const float* Qg = g_q + (long)h  * S_LEN * HEAD_DIM;
    const float* Kg = g_k + (long)kv * S_LEN * HEAD_DIM;
    const float* Vg = g_v + (long)kv * S_LEN * HEAD_DIM;

    // load Q tile (64x128) into Qs (stride 132)
    #pragma unroll
    for (int p = 0; p < 8; ++p) {
        int idx = tid + p * 256;         // 0..2047 float4s
        int row = idx >> 5;
        int c4  = (idx & 31) << 2;
        float4 v = *reinterpret_cast<const float4*>(Qg + (long)(qb * 64 + row) * HEAD_DIM + c4);
        *reinterpret_cast<float4*>(Qs + row * 132 + c4) = v;
    }
    __syncthreads();

    float4 o[8];
    #pragma unroll
    for (int dd = 0; dd < 8; ++dd) o[dd] = make_float4(0.f, 0.f, 0.f, 0.f);
    float m_run = -1e30f, l_run = 0.f;
    const int q_glob = qb * 64 + r;
    const int nkb = 2 * qb + 2;

    for (int kb = 0; kb < nkb; ++kb) {
        // load K,V tiles (32x128 each)
        #pragma unroll
        for (int p = 0; p < 4; ++p) {
            int idx = tid + p * 256;     // 0..1023 float4s
            int row = idx >> 5;
            int c4  = (idx & 31) << 2;
            long g = (long)(kb * 32 + row) * HEAD_DIM + c4;
            *reinterpret_cast<float4*>(Ks + row * 132 + c4) =
                *reinterpret_cast<const float4*>(Kg + g);
            *reinterpret_cast<float4*>(Vs + row * 132 + c4) =
                *reinterpret_cast<const float4*>(Vg + g);
        }
        __syncthreads();

        // S[r][j] for j = t + 4*i
        float s[8];
        #pragma unroll
        for (int i = 0; i < 8; ++i) s[i] = 0.f;
        #pragma unroll 8
        for (int k4 = 0; k4 < 32; ++k4) {
            float4 qv = *reinterpret_cast<float4*>(Qs + r * 132 + k4 * 4);
            #pragma unroll
            for (int i = 0; i < 8; ++i) {
                int j = t + 4 * i;
                float4 kvv = *reinterpret_cast<float4*>(Ks + j * 132 + k4 * 4);
                s[i] += qv.x * kvv.x + qv.y * kvv.y + qv.z * kvv.z + qv.w * kvv.w;
            }
        }

        // scale + causal mask
        float mloc = -1e30f;
        #pragma unroll
        for (int i = 0; i < 8; ++i) {
            int kg = kb * 32 + t + 4 * i;
            s[i] = (kg > q_glob) ? -1e30f : s[i] * ATTN_SCALE;
            mloc = fmaxf(mloc, s[i]);
        }
        mloc = fmaxf(mloc, __shfl_xor_sync(0xffffffffu, mloc, 1, 4));
        mloc = fmaxf(mloc, __shfl_xor_sync(0xffffffffu, mloc, 2, 4));
        float m_new = fmaxf(m_run, mloc);
        float corr = __expf(m_run - m_new);
        float lsum = 0.f;
        #pragma unroll
        for (int i = 0; i < 8; ++i) {
            float pv = __expf(s[i] - m_new);
            lsum += pv;
            Ps[r * 36 + t + 4 * i] = pv;
        }
        lsum += __shfl_xor_sync(0xffffffffu, lsum, 1, 4);
        lsum += __shfl_xor_sync(0xffffffffu, lsum, 2, 4);
        l_run = l_run * corr + lsum;
        m_run = m_new;
        #pragma unroll
        for (int dd = 0; dd < 8; ++dd) {
            o[dd].x *= corr; o[dd].y *= corr; o[dd].z *= corr; o[dd].w *= corr;
        }
        __syncwarp();

        // O += P @ V  (thread owns dim chunks (t + 4*dd)*4)
        #pragma unroll 8
        for (int j = 0; j < 32; ++j) {
            float pv = Ps[r * 36 + j];
            const float4* vrow = reinterpret_cast<const float4*>(Vs + j * 132);
            #pragma unroll
            for (int dd = 0; dd < 8; ++dd) {
                float4 vv = vrow[t + 4 * dd];
                o[dd].x += pv * vv.x; o[dd].y += pv * vv.y;
                o[dd].z += pv * vv.z; o[dd].w += pv * vv.w;
            }
        }
        __syncthreads();
    }

    float inv = 1.f / l_run;
    #pragma unroll
    for (int dd = 0; dd < 8; ++dd) {
        o[dd].x *= inv; o[dd].y *= inv; o[dd].z *= inv; o[dd].w *= inv;
        int d = (t + 4 * dd) * 4;
        *reinterpret_cast<float4*>(g_attn + (long)q_glob * (N_HEADS * HEAD_DIM)
                                   + h * HEAD_DIM + d) = o[dd];
    }
}

// ---------------- output projection -----------------------------------------
__global__ __launch_bounds__(256, 2)
void out_gemm_kernel(const float* __restrict__ Wo, float* __restrict__ out)
{
    __shared__ float As[16 * 132];
    __shared__ float Bs[16 * 132];

    const int m0 = blockIdx.x * 128;
    const int n0 = blockIdx.y * 128;
    const int K = N_HEADS * HEAD_DIM;   // 3584

    float acc[8][8];
    #pragma unroll
    for (int i = 0; i < 8; ++i)
        #pragma unroll
        for (int j = 0; j < 8; ++j) acc[i][j] = 0.f;

    gemm_tile_core(g_attn, Wo + (long)n0 * K, K, m0, acc, As, Bs);

    const int tx = threadIdx.x & 15;
    const int ty = threadIdx.x >> 4;
    #pragma unroll
    for (int i = 0; i < 8; ++i) {
        int m = m0 + ty * 8 + i;
        #pragma unroll
        for (int j = 0; j < 8; ++j)
            out[(long)m * HIDDEN + n0 + tx * 8 + j] = acc[i][j];
    }
}

// ---------------- launch -----------------------------------------------------
extern "C" void kernel_launch(void* const* d_in, const int* in_sizes, int n_in,
                              void* d_out, int out_size)
{
    const float* X    = (const float*)d_in[0];
    const float* cosT = (const float*)d_in[1];
    const float* sinT = (const float*)d_in[2];
    const float* Wq   = (const float*)d_in[3];
    const float* bq   = (const float*)d_in[4];
    const float* Wk   = (const float*)d_in[5];
    const float* bk   = (const float*)d_in[6];
    const float* Wv   = (const float*)d_in[7];
    const float* bv   = (const float*)d_in[8];
    const float* Wo   = (const float*)d_in[9];
    float* out = (float*)d_out;

    // QKV projection: M=2048 (16 tiles), N=4608 (36 tiles)
    qkv_gemm_kernel<<<dim3(16, 36), 256>>>(X, Wq, Wk, Wv, bq, bk, bv);

    // RoPE on q and k
    int rope_threads = (N_HEADS + N_KV) * S_LEN * 64;
    rope_kernel<<<(rope_threads + 255) / 256, 256>>>(cosT, sinT);

    // flash attention
    static bool attr_set = false;
    (void)attr_set;
    cudaFuncSetAttribute(flash_kernel, cudaFuncAttributeMaxDynamicSharedMemorySize,
                         FLASH_SMEM_FLOATS * 4);
    flash_kernel<<<dim3(32, 28), 256, FLASH_SMEM_FLOATS * 4>>>();

    // output projection: M=2048 (16), N=3584 (28)
    out_gemm_kernel<<<dim3(16, 28), 256>>>(Wo, out);
}

// round 4
// speedup vs baseline: 1.4531x; 1.4531x over previous
#include <cuda_runtime.h>
#include <cuda_bf16.h>
#include <cstdint>

#define S_LEN 2048
#define HIDDEN 3584
#define N_HEADS 28
#define N_KV 4
#define HEAD_DIM 128
#define GROUPS 7
#define QKV_N (N_HEADS * HEAD_DIM + 2 * N_KV * HEAD_DIM)   // 4608
#define ATTN_SCALE 0.08838834764831845f

// ===================== device scratch ========================================
__device__ float g_q[N_HEADS * S_LEN * HEAD_DIM];
__device__ float g_k[N_KV * S_LEN * HEAD_DIM];
__device__ float g_v[N_KV * S_LEN * HEAD_DIM];
__device__ float g_attn[S_LEN * N_HEADS * HEAD_DIM];

__device__ __nv_bfloat16 g_x_hi[S_LEN * HIDDEN];
__device__ __nv_bfloat16 g_x_lo[S_LEN * HIDDEN];
__device__ __nv_bfloat16 g_w_hi[QKV_N * HIDDEN];
__device__ __nv_bfloat16 g_w_lo[QKV_N * HIDDEN];
__device__ __nv_bfloat16 g_wo_hi[HIDDEN * HIDDEN];
__device__ __nv_bfloat16 g_wo_lo[HIDDEN * HIDDEN];
__device__ __nv_bfloat16 g_at_hi[S_LEN * HIDDEN];
__device__ __nv_bfloat16 g_at_lo[S_LEN * HIDDEN];

// ===================== low-level helpers =====================================
__device__ __forceinline__ uint32_t smem_u32(const void* p) {
    uint32_t a;
    asm("{ .reg .u64 t; cvta.to.shared.u64 t, %1; cvt.u32.u64 %0, t; }"
        : "=r"(a) : "l"(p));
    return a;
}
__device__ __forceinline__ void cp16(uint32_t s, const void* g) {
    asm volatile("cp.async.cg.shared.global [%0], [%1], 16;" :: "r"(s), "l"(g));
}
#define CP_COMMIT() asm volatile("cp.async.commit_group;" ::: "memory")
#define CP_WAIT1()  asm volatile("cp.async.wait_group 1;" ::: "memory")
#define CP_WAIT0()  asm volatile("cp.async.wait_group 0;" ::: "memory")

__device__ __forceinline__ void ldm4(uint32_t& r0, uint32_t& r1, uint32_t& r2,
                                     uint32_t& r3, uint32_t a) {
    asm volatile("ldmatrix.sync.aligned.m8n8.x4.shared.b16 {%0,%1,%2,%3}, [%4];"
        : "=r"(r0), "=r"(r1), "=r"(r2), "=r"(r3) : "r"(a));
}
__device__ __forceinline__ void mma16816(float* c, const uint32_t* a,
                                         const uint32_t* b) {
    asm volatile(
        "mma.sync.aligned.m16n8k16.row.col.f32.bf16.bf16.f32 "
        "{%0,%1,%2,%3}, {%4,%5,%6,%7}, {%8,%9}, {%0,%1,%2,%3};"
        : "+f"(c[0]), "+f"(c[1]), "+f"(c[2]), "+f"(c[3])
        : "r"(a[0]), "r"(a[1]), "r"(a[2]), "r"(a[3]), "r"(b[0]), "r"(b[1]));
}

// ===================== mma.sync GEMM (bf16 hi/lo split) ======================
// C[m0:+128, n0:+128] = A[m0:+128,:K] @ B[n0:+128,:K]^T, all K-major bf16.
// 3-term split: Ah*Bh + Ah*Bl + Al*Bh, fp32 accumulate.
#define ROW_STRIDE_B 80                 // bytes per smem row (40 bf16)
#define MAT_BYTES (128 * ROW_STRIDE_B)  // 10240
#define STAGE_BYTES (4 * MAT_BYTES)     // 40960
#define STAGES 3
#define GEMM_SMEM (STAGES * STAGE_BYTES)  // 122880

__device__ __forceinline__ void load_stage(
    const __nv_bfloat16* const* ptrs, int K, int kb, uint32_t sbase, int tid)
{
    #pragma unroll
    for (int i = 0; i < 8; ++i) {
        int idx = tid + i * 256;        // 0..2047
        int mat = idx >> 9;             // 0..3
        int rem = idx & 511;
        int row = rem >> 2;
        int cp  = rem & 3;
        const __nv_bfloat16* src = ptrs[mat] + (size_t)row * K + kb + cp * 8;
        cp16(sbase + mat * MAT_BYTES + row * ROW_STRIDE_B + cp * 16, src);
    }
}

__device__ __forceinline__ void compute_stage(
    uint32_t sbase, int warp_m, int warp_n, int lane, float acc[2][8][4])
{
    const uint32_t ahB = sbase;
    const uint32_t alB = sbase + MAT_BYTES;
    const uint32_t bhB = sbase + 2 * MAT_BYTES;
    const uint32_t blB = sbase + 3 * MAT_BYTES;

    const int lrow = lane & 15;
    const int lk   = (lane >> 4) * 8;           // A-frag k half
    const int g    = lane >> 3;
    const int nadd = ((g >> 1) << 3) + (lane & 7);
    const int kadd = (g & 1) * 8;               // B-frag k half

    #pragma unroll
    for (int ks = 0; ks < 2; ++ks) {
        uint32_t ah[2][4], al[2][4], bh[8][2], bl[8][2];
        #pragma unroll
        for (int mf = 0; mf < 2; ++mf) {
            uint32_t off = (uint32_t)(warp_m * 32 + mf * 16 + lrow) * ROW_STRIDE_B
                         + (ks * 16 + lk) * 2;
            ldm4(ah[mf][0], ah[mf][1], ah[mf][2], ah[mf][3], ahB + off);
            ldm4(al[mf][0], al[mf][1], al[mf][2], al[mf][3], alB + off);
        }
        #pragma unroll
        for (int nf2 = 0; nf2 < 4; ++nf2) {
            uint32_t off = (uint32_t)(warp_n * 64 + nf2 * 16 + nadd) * ROW_STRIDE_B
                         + (ks * 16 + kadd) * 2;
            ldm4(bh[nf2*2][0], bh[nf2*2][1], bh[nf2*2+1][0], bh[nf2*2+1][1], bhB + off);
            ldm4(bl[nf2*2][0], bl[nf2*2][1], bl[nf2*2+1][0], bl[nf2*2+1][1], blB + off);
        }
        #pragma unroll
        for (int mf = 0; mf < 2; ++mf)
            #pragma unroll
            for (int nf = 0; nf < 8; ++nf) {
                mma16816(acc[mf][nf], ah[mf], bh[nf]);
                mma16816(acc[mf][nf], ah[mf], bl[nf]);
                mma16816(acc[mf][nf], al[mf], bh[nf]);
            }
    }
}

// mainloop: A/B pointers must already include the tile offsets (m0/n0 rows)
__device__ __forceinline__ void gemm_main(
    const __nv_bfloat16* ahi, const __nv_bfloat16* alo,
    const __nv_bfloat16* bhi, const __nv_bfloat16* blo,
    int K, char* sm, float acc[2][8][4])
{
    const int tid = threadIdx.x;
    const int wid = tid >> 5;
    const int lane = tid & 31;
    const int warp_m = wid & 3;
    const int warp_n = wid >> 2;
    const uint32_t smb = smem_u32(sm);

    const __nv_bfloat16* ptrs[4] = {ahi, alo, bhi, blo};

    #pragma unroll
    for (int mf = 0; mf < 2; ++mf)
        #pragma unroll
        for (int nf = 0; nf < 8; ++nf)
            #pragma unroll
            for (int r = 0; r < 4; ++r) acc[mf][nf][r] = 0.f;

    const int nIters = K / 32;
    load_stage(ptrs, K, 0, smb, tid);
    CP_COMMIT();
    load_stage(ptrs, K, 32, smb + STAGE_BYTES, tid);
    CP_COMMIT();

    for (int c = 0; c < nIters; ++c) {
        CP_WAIT1();
        __syncthreads();
        compute_stage(smb + (c % 3) * STAGE_BYTES, warp_m, warp_n, lane, acc);
        __syncthreads();
        if (c + 2 < nIters)
            load_stage(ptrs, K, (c + 2) * 32, smb + ((c + 2) % 3) * STAGE_BYTES, tid);
        CP_COMMIT();
    }
    CP_WAIT0();
}

// ===================== QKV projection =======================================
__global__ __launch_bounds__(256, 1)
void qkv_mma_kernel(const float* __restrict__ bq, const float* __restrict__ bk,
                    const float* __restrict__ bv)
{
    extern __shared__ __align__(128) char sm[];
    const int m0 = blockIdx.x * 128;
    const int n0 = blockIdx.y * 128;

    float acc[2][8][4];
    gemm_main(g_x_hi + (size_t)m0 * HIDDEN,           // FIX: m0 row offset
              g_x_lo + (size_t)m0 * HIDDEN,
              g_w_hi + (size_t)n0 * HIDDEN,
              g_w_lo + (size_t)n0 * HIDDEN,
              HIDDEN, sm, acc);

    float* dst;
    const float* bias;
    if (n0 < N_HEADS * HEAD_DIM) {
        dst = g_q + (size_t)(n0 >> 7) * S_LEN * HEAD_DIM; bias = bq + n0;
    } else if (n0 < (N_HEADS + N_KV) * HEAD_DIM) {
        int o = n0 - N_HEADS * HEAD_DIM;
        dst = g_k + (size_t)(o >> 7) * S_LEN * HEAD_DIM; bias = bk + o;
    } else {
        int o = n0 - (N_HEADS + N_KV) * HEAD_DIM;
        dst = g_v + (size_t)(o >> 7) * S_LEN * HEAD_DIM; bias = bv + o;
    }

    const int tid = threadIdx.x;
    const int wid = tid >> 5;
    const int lane = tid & 31;
    const int warp_m = wid & 3;
    const int warp_n = wid >> 2;

    #pragma unroll
    for (int mf = 0; mf < 2; ++mf) {
        int row = m0 + warp_m * 32 + mf * 16 + (lane >> 2);
        #pragma unroll
        for (int nf = 0; nf < 8; ++nf) {
            int col = warp_n * 64 + nf * 8 + (lane & 3) * 2;   // 0..127
            float b0 = bias[col], b1 = bias[col + 1];
            dst[(size_t)row * HEAD_DIM + col]           = acc[mf][nf][0] + b0;
            dst[(size_t)row * HEAD_DIM + col + 1]       = acc[mf][nf][1] + b1;
            dst[(size_t)(row + 8) * HEAD_DIM + col]     = acc[mf][nf][2] + b0;
            dst[(size_t)(row + 8) * HEAD_DIM + col + 1] = acc[mf][nf][3] + b1;
        }
    }
}

// ===================== output projection ====================================
__global__ __launch_bounds__(256, 1)
void out_mma_kernel(float* __restrict__ out)
{
    extern __shared__ __align__(128) char sm[];
    const int m0 = blockIdx.x * 128;
    const int n0 = blockIdx.y * 128;

    float acc[2][8][4];
    gemm_main(g_at_hi + (size_t)m0 * HIDDEN,          // FIX: m0 row offset
              g_at_lo + (size_t)m0 * HIDDEN,
              g_wo_hi + (size_t)n0 * HIDDEN,
              g_wo_lo + (size_t)n0 * HIDDEN,
              HIDDEN, sm, acc);

    const int tid = threadIdx.x;
    const int wid = tid >> 5;
    const int lane = tid & 31;
    const int warp_m = wid & 3;
    const int warp_n = wid >> 2;

    #pragma unroll
    for (int mf = 0; mf < 2; ++mf) {
        int row = m0 + warp_m * 32 + mf * 16 + (lane >> 2);
        #pragma unroll
        for (int nf = 0; nf < 8; ++nf) {
            int col = n0 + warp_n * 64 + nf * 8 + (lane & 3) * 2;
            out[(size_t)row * HIDDEN + col]           = acc[mf][nf][0];
            out[(size_t)row * HIDDEN + col + 1]       = acc[mf][nf][1];
            out[(size_t)(row + 8) * HIDDEN + col]     = acc[mf][nf][2];
            out[(size_t)(row + 8) * HIDDEN + col + 1] = acc[mf][nf][3];
        }
    }
}

// ===================== fp32 -> bf16 hi/lo split ==============================
__global__ void cvt_split_kernel(const float* __restrict__ src,
                                 __nv_bfloat16* __restrict__ hi,
                                 __nv_bfloat16* __restrict__ lo, int n4)
{
    int i = blockIdx.x * blockDim.x + threadIdx.x;
    if (i >= n4) return;
    float4 v = reinterpret_cast<const float4*>(src)[i];
    __nv_bfloat16 h0 = __float2bfloat16(v.x);
    __nv_bfloat16 h1 = __float2bfloat16(v.y);
    __nv_bfloat16 h2 = __float2bfloat16(v.z);
    __nv_bfloat16 h3 = __float2bfloat16(v.w);
    __nv_bfloat16 l0 = __float2bfloat16(v.x - __bfloat162float(h0));
    __nv_bfloat16 l1 = __float2bfloat16(v.y - __bfloat162float(h1));
    __nv_bfloat16 l2 = __float2bfloat16(v.z - __bfloat162float(h2));
    __nv_bfloat16 l3 = __float2bfloat16(v.w - __bfloat162float(h3));
    ushort4 hv, lv;
    hv.x = __bfloat16_as_ushort(h0); hv.y = __bfloat16_as_ushort(h1);
    hv.z = __bfloat16_as_ushort(h2); hv.w = __bfloat16_as_ushort(h3);
    lv.x = __bfloat16_as_ushort(l0); lv.y = __bfloat16_as_ushort(l1);
    lv.z = __bfloat16_as_ushort(l2); lv.w = __bfloat16_as_ushort(l3);
    reinterpret_cast<ushort4*>(hi)[i] = hv;
    reinterpret_cast<ushort4*>(lo)[i] = lv;
}

// ===================== RoPE ==================================================
__global__ void rope_kernel(const float* __restrict__ cos_t,
                            const float* __restrict__ sin_t)
{
    int idx = blockIdx.x * blockDim.x + threadIdx.x;
    if (idx >= (N_HEADS + N_KV) * S_LEN * 64) return;
    int d = idx & 63;
    int s = (idx >> 6) & (S_LEN - 1);
    int head = idx >> 17;
    float* p = (head < N_HEADS) ? (g_q + (long)head * S_LEN * HEAD_DIM)
                                : (g_k + (long)(head - N_HEADS) * S_LEN * HEAD_DIM);
    float c  = cos_t[s * HEAD_DIM + d];
    float sn = sin_t[s * HEAD_DIM + d];
    float x1 = p[(long)s * HEAD_DIM + d];
    float x2 = p[(long)s * HEAD_DIM + d + 64];
    p[(long)s * HEAD_DIM + d]      = x1 * c - x2 * sn;
    p[(long)s * HEAD_DIM + d + 64] = x2 * c + x1 * sn;
}

// ===================== flash attention (fp32 SIMT) ===========================
#define FLASH_SMEM_FLOATS (64 * 132 + 32 * 132 + 32 * 132 + 64 * 36)

__global__ __launch_bounds__(256, 2)
void flash_kernel()
{
    extern __shared__ float smf[];
    float* Qs = smf;
    float* Ks = Qs + 64 * 132;
    float* Vs = Ks + 32 * 132;
    float* Ps = Vs + 32 * 132;

    const int qb = blockIdx.x;
    const int h  = blockIdx.y;
    const int kv = h / GROUPS;
    const int tid = threadIdx.x;
    const int r = tid >> 2;
    const int t = tid & 3;

    const float* Qg = g_q + (long)h  * S_LEN * HEAD_DIM;
    const float* Kg = g_k + (long)kv * S_LEN * HEAD_DIM;
    const float* Vg = g_v + (long)kv * S_LEN * HEAD_DIM;

    #pragma unroll
    for (int p = 0; p < 8; ++p) {
        int idx = tid + p * 256;
        int row = idx >> 5;
        int c4  = (idx & 31) << 2;
        float4 v = *reinterpret_cast<const float4*>(Qg + (long)(qb * 64 + row) * HEAD_DIM + c4);
        *reinterpret_cast<float4*>(Qs + row * 132 + c4) = v;
    }
    __syncthreads();

    float4 o[8];
    #pragma unroll
    for (int dd = 0; dd < 8; ++dd) o[dd] = make_float4(0.f, 0.f, 0.f, 0.f);
    float m_run = -1e30f, l_run = 0.f;
    const int q_glob = qb * 64 + r;
    const int nkb = 2 * qb + 2;

    for (int kb = 0; kb < nkb; ++kb) {
        #pragma unroll
        for (int p = 0; p < 4; ++p) {
            int idx = tid + p * 256;
            int row = idx >> 5;
            int c4  = (idx & 31) << 2;
            long g = (long)(kb * 32 + row) * HEAD_DIM + c4;
            *reinterpret_cast<float4*>(Ks + row * 132 + c4) =
                *reinterpret_cast<const float4*>(Kg + g);
            *reinterpret_cast<float4*>(Vs + row * 132 + c4) =
                *reinterpret_cast<const float4*>(Vg + g);
        }
        __syncthreads();

        float s[8];
        #pragma unroll
        for (int i = 0; i < 8; ++i) s[i] = 0.f;
        #pragma unroll 8
        for (int k4 = 0; k4 < 32; ++k4) {
            float4 qv = *reinterpret_cast<float4*>(Qs + r * 132 + k4 * 4);
            #pragma unroll
            for (int i = 0; i < 8; ++i) {
                int j = t + 4 * i;
                float4 kvv = *reinterpret_cast<float4*>(Ks + j * 132 + k4 * 4);
                s[i] += qv.x * kvv.x + qv.y * kvv.y + qv.z * kvv.z + qv.w * kvv.w;
            }
        }

        float mloc = -1e30f;
        #pragma unroll
        for (int i = 0; i < 8; ++i) {
            int kg = kb * 32 + t + 4 * i;
            s[i] = (kg > q_glob) ? -1e30f : s[i] * ATTN_SCALE;
            mloc = fmaxf(mloc, s[i]);
        }
        mloc = fmaxf(mloc, __shfl_xor_sync(0xffffffffu, mloc, 1, 4));
        mloc = fmaxf(mloc, __shfl_xor_sync(0xffffffffu, mloc, 2, 4));
        float m_new = fmaxf(m_run, mloc);
        float corr = __expf(m_run - m_new);
        float lsum = 0.f;
        #pragma unroll
        for (int i = 0; i < 8; ++i) {
            float pv = __expf(s[i] - m_new);
            lsum += pv;
            Ps[r * 36 + t + 4 * i] = pv;
        }
        lsum += __shfl_xor_sync(0xffffffffu, lsum, 1, 4);
        lsum += __shfl_xor_sync(0xffffffffu, lsum, 2, 4);
        l_run = l_run * corr + lsum;
        m_run = m_new;
        #pragma unroll
        for (int dd = 0; dd < 8; ++dd) {
            o[dd].x *= corr; o[dd].y *= corr; o[dd].z *= corr; o[dd].w *= corr;
        }
        __syncwarp();

        #pragma unroll 8
        for (int j = 0; j < 32; ++j) {
            float pv = Ps[r * 36 + j];
            const float4* vrow = reinterpret_cast<const float4*>(Vs + j * 132);
            #pragma unroll
            for (int dd = 0; dd < 8; ++dd) {
                float4 vv = vrow[t + 4 * dd];
                o[dd].x += pv * vv.x; o[dd].y += pv * vv.y;
                o[dd].z += pv * vv.z; o[dd].w += pv * vv.w;
            }
        }
        __syncthreads();
    }

    float inv = 1.f / l_run;
    #pragma unroll
    for (int dd = 0; dd < 8; ++dd) {
        o[dd].x *= inv; o[dd].y *= inv; o[dd].z *= inv; o[dd].w *= inv;
        int d = (t + 4 * dd) * 4;
        *reinterpret_cast<float4*>(g_attn + (long)q_glob * (N_HEADS * HEAD_DIM)
                                   + h * HEAD_DIM + d) = o[dd];
    }
}

// ===================== launch ================================================
extern "C" void kernel_launch(void* const* d_in, const int* in_sizes, int n_in,
                              void* d_out, int out_size)
{
    const float* X    = (const float*)d_in[0];
    const float* cosT = (const float*)d_in[1];
    const float* sinT = (const float*)d_in[2];
    const float* Wq   = (const float*)d_in[3];
    const float* bq   = (const float*)d_in[4];
    const float* Wk   = (const float*)d_in[5];
    const float* bk   = (const float*)d_in[6];
    const float* Wv   = (const float*)d_in[7];
    const float* bv   = (const float*)d_in[8];
    const float* Wo   = (const float*)d_in[9];
    float* out = (float*)d_out;

    __nv_bfloat16 *x_hi, *x_lo, *w_hi, *w_lo, *wo_hi, *wo_lo, *at_hi, *at_lo;
    float* attn;
    cudaGetSymbolAddress((void**)&x_hi,  g_x_hi);
    cudaGetSymbolAddress((void**)&x_lo,  g_x_lo);
    cudaGetSymbolAddress((void**)&w_hi,  g_w_hi);
    cudaGetSymbolAddress((void**)&w_lo,  g_w_lo);
    cudaGetSymbolAddress((void**)&wo_hi, g_wo_hi);
    cudaGetSymbolAddress((void**)&wo_lo, g_wo_lo);
    cudaGetSymbolAddress((void**)&at_hi, g_at_hi);
    cudaGetSymbolAddress((void**)&at_lo, g_at_lo);
    cudaGetSymbolAddress((void**)&attn,  g_attn);

    cudaFuncSetAttribute(qkv_mma_kernel, cudaFuncAttributeMaxDynamicSharedMemorySize, GEMM_SMEM);
    cudaFuncSetAttribute(out_mma_kernel, cudaFuncAttributeMaxDynamicSharedMemorySize, GEMM_SMEM);
    cudaFuncSetAttribute(flash_kernel,   cudaFuncAttributeMaxDynamicSharedMemorySize, FLASH_SMEM_FLOATS * 4);

    // 1) convert inputs to bf16 hi/lo
    {
        int n4 = S_LEN * HIDDEN / 4;
        cvt_split_kernel<<<(n4 + 255) / 256, 256>>>(X, x_hi, x_lo, n4);
    }
    {
        int n4 = (N_HEADS * HEAD_DIM) * HIDDEN / 4;
        cvt_split_kernel<<<(n4 + 255) / 256, 256>>>(Wq, w_hi, w_lo, n4);
        int off = N_HEADS * HEAD_DIM * HIDDEN;
        int m4 = (N_KV * HEAD_DIM) * HIDDEN / 4;
        cvt_split_kernel<<<(m4 + 255) / 256, 256>>>(Wk, w_hi + off, w_lo + off, m4);
        off += N_KV * HEAD_DIM * HIDDEN;
        cvt_split_kernel<<<(m4 + 255) / 256, 256>>>(Wv, w_hi + off, w_lo + off, m4);
    }
    {
        int n4 = HIDDEN * HIDDEN / 4;
        cvt_split_kernel<<<(n4 + 255) / 256, 256>>>(Wo, wo_hi, wo_lo, n4);
    }

    // 2) QKV projection (mma.sync tensor cores)
    qkv_mma_kernel<<<dim3(16, 36), 256, GEMM_SMEM>>>(bq, bk, bv);

    // 3) RoPE
    int rope_threads = (N_HEADS + N_KV) * S_LEN * 64;
    rope_kernel<<<(rope_threads + 255) / 256, 256>>>(cosT, sinT);

    // 4) flash attention (fp32 SIMT)
    flash_kernel<<<dim3(32, 28), 256, FLASH_SMEM_FLOATS * 4>>>();

    // 5) attention output conversion + output projection
    {
        int n4 = S_LEN * HIDDEN / 4;
        cvt_split_kernel<<<(n4 + 255) / 256, 256>>>(attn, at_hi, at_lo, n4);
    }
    out_mma_kernel<<<dim3(16, 28), 256, GEMM_SMEM>>>(out);
}

// round 5
// speedup vs baseline: 3.1558x; 2.1718x over previous
#include <cuda_runtime.h>
#include <cuda_bf16.h>
#include <cstdint>

#define S_LEN 2048
#define HIDDEN 3584
#define N_HEADS 28
#define N_KV 4
#define HEAD_DIM 128
#define GROUPS 7
#define QKV_N (N_HEADS * HEAD_DIM + 2 * N_KV * HEAD_DIM)   // 4608
#define ATTN_SCALE 0.08838834764831845f

// ===================== device scratch ========================================
__device__ float g_q[N_HEADS * S_LEN * HEAD_DIM];
__device__ float g_k[N_KV * S_LEN * HEAD_DIM];
__device__ float g_v[N_KV * S_LEN * HEAD_DIM];

__device__ __nv_bfloat16 g_x_hi[S_LEN * HIDDEN];
__device__ __nv_bfloat16 g_x_lo[S_LEN * HIDDEN];
__device__ __nv_bfloat16 g_w_hi[QKV_N * HIDDEN];
__device__ __nv_bfloat16 g_w_lo[QKV_N * HIDDEN];
__device__ __nv_bfloat16 g_wo_hi[HIDDEN * HIDDEN];
__device__ __nv_bfloat16 g_wo_lo[HIDDEN * HIDDEN];
__device__ __nv_bfloat16 g_at_hi[S_LEN * HIDDEN];
__device__ __nv_bfloat16 g_at_lo[S_LEN * HIDDEN];

// bf16 hi/lo attention operands
__device__ __nv_bfloat16 g_q_hi[N_HEADS * S_LEN * HEAD_DIM];
__device__ __nv_bfloat16 g_q_lo[N_HEADS * S_LEN * HEAD_DIM];
__device__ __nv_bfloat16 g_k_hi[N_KV * S_LEN * HEAD_DIM];
__device__ __nv_bfloat16 g_k_lo[N_KV * S_LEN * HEAD_DIM];
__device__ __nv_bfloat16 g_vT_hi[N_KV * HEAD_DIM * S_LEN];   // [kv][d][s]
__device__ __nv_bfloat16 g_vT_lo[N_KV * HEAD_DIM * S_LEN];

// ===================== low-level helpers =====================================
__device__ __forceinline__ uint32_t smem_u32(const void* p) {
    uint32_t a;
    asm("{ .reg .u64 t; cvta.to.shared.u64 t, %1; cvt.u32.u64 %0, t; }"
        : "=r"(a) : "l"(p));
    return a;
}
__device__ __forceinline__ void cp16(uint32_t s, const void* g) {
    asm volatile("cp.async.cg.shared.global [%0], [%1], 16;" :: "r"(s), "l"(g));
}
#define CP_COMMIT() asm volatile("cp.async.commit_group;" ::: "memory")
#define CP_WAIT1()  asm volatile("cp.async.wait_group 1;" ::: "memory")
#define CP_WAIT0()  asm volatile("cp.async.wait_group 0;" ::: "memory")

__device__ __forceinline__ void ldm4(uint32_t& r0, uint32_t& r1, uint32_t& r2,
                                     uint32_t& r3, uint32_t a) {
    asm volatile("ldmatrix.sync.aligned.m8n8.x4.shared.b16 {%0,%1,%2,%3}, [%4];"
        : "=r"(r0), "=r"(r1), "=r"(r2), "=r"(r3) : "r"(a));
}
__device__ __forceinline__ void mma16816(float* c, const uint32_t* a,
                                         const uint32_t* b) {
    asm volatile(
        "mma.sync.aligned.m16n8k16.row.col.f32.bf16.bf16.f32 "
        "{%0,%1,%2,%3}, {%4,%5,%6,%7}, {%8,%9}, {%0,%1,%2,%3};"
        : "+f"(c[0]), "+f"(c[1]), "+f"(c[2]), "+f"(c[3])
        : "r"(a[0]), "r"(a[1]), "r"(a[2]), "r"(a[3]), "r"(b[0]), "r"(b[1]));
}

__device__ __forceinline__ uint32_t pack_hilo(float x, float y, uint32_t& lo) {
    __nv_bfloat16 hx = __float2bfloat16(x);
    __nv_bfloat16 hy = __float2bfloat16(y);
    __nv_bfloat16 lx = __float2bfloat16(x - __bfloat162float(hx));
    __nv_bfloat16 ly = __float2bfloat16(y - __bfloat162float(hy));
    lo = (uint32_t)__bfloat16_as_ushort(lx) | ((uint32_t)__bfloat16_as_ushort(ly) << 16);
    return (uint32_t)__bfloat16_as_ushort(hx) | ((uint32_t)__bfloat16_as_ushort(hy) << 16);
}

// ===================== mma.sync GEMM (bf16 hi/lo split) ======================
#define ROW_STRIDE_B 80
#define MAT_BYTES (128 * ROW_STRIDE_B)
#define STAGE_BYTES (4 * MAT_BYTES)
#define GEMM_SMEM (3 * STAGE_BYTES)

__device__ __forceinline__ void load_stage(
    const __nv_bfloat16* const* ptrs, int K, int kb, uint32_t sbase, int tid)
{
    #pragma unroll
    for (int i = 0; i < 8; ++i) {
        int idx = tid + i * 256;
        int mat = idx >> 9;
        int rem = idx & 511;
        int row = rem >> 2;
        int cp  = rem & 3;
        const __nv_bfloat16* src = ptrs[mat] + (size_t)row * K + kb + cp * 8;
        cp16(sbase + mat * MAT_BYTES + row * ROW_STRIDE_B + cp * 16, src);
    }
}

__device__ __forceinline__ void compute_stage(
    uint32_t sbase, int warp_m, int warp_n, int lane, float acc[2][8][4])
{
    const uint32_t ahB = sbase;
    const uint32_t alB = sbase + MAT_BYTES;
    const uint32_t bhB = sbase + 2 * MAT_BYTES;
    const uint32_t blB = sbase + 3 * MAT_BYTES;

    const int lrow = lane & 15;
    const int lk   = (lane >> 4) * 8;
    const int g    = lane >> 3;
    const int nadd = ((g >> 1) << 3) + (lane & 7);
    const int kadd = (g & 1) * 8;

    #pragma unroll
    for (int ks = 0; ks < 2; ++ks) {
        uint32_t ah[2][4], al[2][4], bh[8][2], bl[8][2];
        #pragma unroll
        for (int mf = 0; mf < 2; ++mf) {
            uint32_t off = (uint32_t)(warp_m * 32 + mf * 16 + lrow) * ROW_STRIDE_B
                         + (ks * 16 + lk) * 2;
            ldm4(ah[mf][0], ah[mf][1], ah[mf][2], ah[mf][3], ahB + off);
            ldm4(al[mf][0], al[mf][1], al[mf][2], al[mf][3], alB + off);
        }
        #pragma unroll
        for (int nf2 = 0; nf2 < 4; ++nf2) {
            uint32_t off = (uint32_t)(warp_n * 64 + nf2 * 16 + nadd) * ROW_STRIDE_B
                         + (ks * 16 + kadd) * 2;
            ldm4(bh[nf2*2][0], bh[nf2*2][1], bh[nf2*2+1][0], bh[nf2*2+1][1], bhB + off);
            ldm4(bl[nf2*2][0], bl[nf2*2][1], bl[nf2*2+1][0], bl[nf2*2+1][1], blB + off);
        }
        #pragma unroll
        for (int mf = 0; mf < 2; ++mf)
            #pragma unroll
            for (int nf = 0; nf < 8; ++nf) {
                mma16816(acc[mf][nf], ah[mf], bh[nf]);
                mma16816(acc[mf][nf], ah[mf], bl[nf]);
                mma16816(acc[mf][nf], al[mf], bh[nf]);
            }
    }
}

__device__ __forceinline__ void gemm_main(
    const __nv_bfloat16* ahi, const __nv_bfloat16* alo,
    const __nv_bfloat16* bhi, const __nv_bfloat16* blo,
    int K, char* sm, float acc[2][8][4])
{
    const int tid = threadIdx.x;
    const int wid = tid >> 5;
    const int lane = tid & 31;
    const int warp_m = wid & 3;
    const int warp_n = wid >> 2;
    const uint32_t smb = smem_u32(sm);

    const __nv_bfloat16* ptrs[4] = {ahi, alo, bhi, blo};

    #pragma unroll
    for (int mf = 0; mf < 2; ++mf)
        #pragma unroll
        for (int nf = 0; nf < 8; ++nf)
            #pragma unroll
            for (int r = 0; r < 4; ++r) acc[mf][nf][r] = 0.f;

    const int nIters = K / 32;
    load_stage(ptrs, K, 0, smb, tid);
    CP_COMMIT();
    load_stage(ptrs, K, 32, smb + STAGE_BYTES, tid);
    CP_COMMIT();

    for (int c = 0; c < nIters; ++c) {
        CP_WAIT1();
        __syncthreads();
        compute_stage(smb + (c % 3) * STAGE_BYTES, warp_m, warp_n, lane, acc);
        __syncthreads();
        if (c + 2 < nIters)
            load_stage(ptrs, K, (c + 2) * 32, smb + ((c + 2) % 3) * STAGE_BYTES, tid);
        CP_COMMIT();
    }
    CP_WAIT0();
}

// ===================== QKV projection =======================================
__global__ __launch_bounds__(256, 1)
void qkv_mma_kernel(const float* __restrict__ bq, const float* __restrict__ bk,
                    const float* __restrict__ bv)
{
    extern __shared__ __align__(128) char sm[];
    const int m0 = blockIdx.x * 128;
    const int n0 = blockIdx.y * 128;

    float acc[2][8][4];
    gemm_main(g_x_hi + (size_t)m0 * HIDDEN,
              g_x_lo + (size_t)m0 * HIDDEN,
              g_w_hi + (size_t)n0 * HIDDEN,
              g_w_lo + (size_t)n0 * HIDDEN,
              HIDDEN, sm, acc);

    float* dst;
    const float* bias;
    if (n0 < N_HEADS * HEAD_DIM) {
        dst = g_q + (size_t)(n0 >> 7) * S_LEN * HEAD_DIM; bias = bq + n0;
    } else if (n0 < (N_HEADS + N_KV) * HEAD_DIM) {
        int o = n0 - N_HEADS * HEAD_DIM;
        dst = g_k + (size_t)(o >> 7) * S_LEN * HEAD_DIM; bias = bk + o;
    } else {
        int o = n0 - (N_HEADS + N_KV) * HEAD_DIM;
        dst = g_v + (size_t)(o >> 7) * S_LEN * HEAD_DIM; bias = bv + o;
    }

    const int tid = threadIdx.x;
    const int wid = tid >> 5;
    const int lane = tid & 31;
    const int warp_m = wid & 3;
    const int warp_n = wid >> 2;

    #pragma unroll
    for (int mf = 0; mf < 2; ++mf) {
        int row = m0 + warp_m * 32 + mf * 16 + (lane >> 2);
        #pragma unroll
        for (int nf = 0; nf < 8; ++nf) {
            int col = warp_n * 64 + nf * 8 + (lane & 3) * 2;
            float b0 = bias[col], b1 = bias[col + 1];
            dst[(size_t)row * HEAD_DIM + col]           = acc[mf][nf][0] + b0;
            dst[(size_t)row * HEAD_DIM + col + 1]       = acc[mf][nf][1] + b1;
            dst[(size_t)(row + 8) * HEAD_DIM + col]     = acc[mf][nf][2] + b0;
            dst[(size_t)(row + 8) * HEAD_DIM + col + 1] = acc[mf][nf][3] + b1;
        }
    }
}

// ===================== output projection ====================================
__global__ __launch_bounds__(256, 1)
void out_mma_kernel(float* __restrict__ out)
{
    extern __shared__ __align__(128) char sm[];
    const int m0 = blockIdx.x * 128;
    const int n0 = blockIdx.y * 128;

    float acc[2][8][4];
    gemm_main(g_at_hi + (size_t)m0 * HIDDEN,
              g_at_lo + (size_t)m0 * HIDDEN,
              g_wo_hi + (size_t)n0 * HIDDEN,
              g_wo_lo + (size_t)n0 * HIDDEN,
              HIDDEN, sm, acc);

    const int tid = threadIdx.x;
    const int wid = tid >> 5;
    const int lane = tid & 31;
    const int warp_m = wid & 3;
    const int warp_n = wid >> 2;

    #pragma unroll
    for (int mf = 0; mf < 2; ++mf) {
        int row = m0 + warp_m * 32 + mf * 16 + (lane >> 2);
        #pragma unroll
        for (int nf = 0; nf < 8; ++nf) {
            int col = n0 + warp_n * 64 + nf * 8 + (lane & 3) * 2;
            out[(size_t)row * HIDDEN + col]           = acc[mf][nf][0];
            out[(size_t)row * HIDDEN + col + 1]       = acc[mf][nf][1];
            out[(size_t)(row + 8) * HIDDEN + col]     = acc[mf][nf][2];
            out[(size_t)(row + 8) * HIDDEN + col + 1] = acc[mf][nf][3];
        }
    }
}

// ===================== fp32 -> bf16 hi/lo split ==============================
__global__ void cvt_split_kernel(const float* __restrict__ src,
                                 __nv_bfloat16* __restrict__ hi,
                                 __nv_bfloat16* __restrict__ lo, int n4)
{
    int i = blockIdx.x * blockDim.x + threadIdx.x;
    if (i >= n4) return;
    float4 v = reinterpret_cast<const float4*>(src)[i];
    __nv_bfloat16 h0 = __float2bfloat16(v.x);
    __nv_bfloat16 h1 = __float2bfloat16(v.y);
    __nv_bfloat16 h2 = __float2bfloat16(v.z);
    __nv_bfloat16 h3 = __float2bfloat16(v.w);
    __nv_bfloat16 l0 = __float2bfloat16(v.x - __bfloat162float(h0));
    __nv_bfloat16 l1 = __float2bfloat16(v.y - __bfloat162float(h1));
    __nv_bfloat16 l2 = __float2bfloat16(v.z - __bfloat162float(h2));
    __nv_bfloat16 l3 = __float2bfloat16(v.w - __bfloat162float(h3));
    ushort4 hv, lv;
    hv.x = __bfloat16_as_ushort(h0); hv.y = __bfloat16_as_ushort(h1);
    hv.z = __bfloat16_as_ushort(h2); hv.w = __bfloat16_as_ushort(h3);
    lv.x = __bfloat16_as_ushort(l0); lv.y = __bfloat16_as_ushort(l1);
    lv.z = __bfloat16_as_ushort(l2); lv.w = __bfloat16_as_ushort(l3);
    reinterpret_cast<ushort4*>(hi)[i] = hv;
    reinterpret_cast<ushort4*>(lo)[i] = lv;
}

// ===================== RoPE + convert to hi/lo bf16 ==========================
__global__ void rope_cvt_kernel(const float* __restrict__ cos_t,
                                const float* __restrict__ sin_t)
{
    int idx = blockIdx.x * blockDim.x + threadIdx.x;
    if (idx >= (N_HEADS + N_KV) * S_LEN * 64) return;
    int d = idx & 63;
    int s = (idx >> 6) & (S_LEN - 1);
    int head = idx >> 17;

    const float* p;
    __nv_bfloat16 *hi, *lo;
    size_t base;
    if (head < N_HEADS) {
        base = (size_t)head * S_LEN * HEAD_DIM;
        p = g_q + base; hi = g_q_hi + base; lo = g_q_lo + base;
    } else {
        base = (size_t)(head - N_HEADS) * S_LEN * HEAD_DIM;
        p = g_k + base; hi = g_k_hi + base; lo = g_k_lo + base;
    }
    float c  = cos_t[s * HEAD_DIM + d];
    float sn = sin_t[s * HEAD_DIM + d];
    float x1 = p[(size_t)s * HEAD_DIM + d];
    float x2 = p[(size_t)s * HEAD_DIM + d + 64];
    float y1 = x1 * c - x2 * sn;
    float y2 = x2 * c + x1 * sn;
    __nv_bfloat16 h1 = __float2bfloat16(y1);
    __nv_bfloat16 h2 = __float2bfloat16(y2);
    size_t o1 = (size_t)s * HEAD_DIM + d;
    size_t o2 = o1 + 64;
    hi[o1] = h1; lo[o1] = __float2bfloat16(y1 - __bfloat162float(h1));
    hi[o2] = h2; lo[o2] = __float2bfloat16(y2 - __bfloat162float(h2));
}

// ===================== V transpose + convert =================================
__global__ void v_cvt_kernel()
{
    int idx = blockIdx.x * blockDim.x + threadIdx.x;
    if (idx >= N_KV * S_LEN * HEAD_DIM) return;
    int kv = idx >> 18;
    int rem = idx & (S_LEN * HEAD_DIM - 1);
    int s = rem >> 7;
    int d = rem & 127;
    float v = g_v[idx];
    __nv_bfloat16 h = __float2bfloat16(v);
    size_t o = (size_t)kv * HEAD_DIM * S_LEN + (size_t)d * S_LEN + s;
    g_vT_hi[o] = h;
    g_vT_lo[o] = __float2bfloat16(v - __bfloat162float(h));
}

// ===================== flash attention (mma.sync, hi/lo split) ===============
// smem: Qh 128x272B, Ql, Kh 64x272B, Kl, Vh 128x144B, Vl = 141312 bytes
#define FL_QH 0u
#define FL_QL 34816u
#define FL_KH 69632u
#define FL_KL 87040u
#define FL_VH 104448u
#define FL_VL 122880u
#define FLASH_SMEM 141312

__global__ __launch_bounds__(256, 1)
void flash_mma_kernel()
{
    extern __shared__ __align__(128) char sm[];
    const uint32_t smb = smem_u32(sm);
    const int qb  = 15 - (int)blockIdx.x;      // big tiles first
    const int h   = blockIdx.y;
    const int kvh = h / GROUPS;
    const int tid = threadIdx.x;
    const int wid = tid >> 5;
    const int lane = tid & 31;
    const int lrow = lane & 15;
    const int lk   = (lane >> 4) * 8;
    const int g    = lane >> 3;
    const int nadd = ((g >> 1) << 3) + (lane & 7);
    const int kadd = (g & 1) * 8;

    // load Q tile (128 x 128) hi/lo
    const __nv_bfloat16* qh_g = g_q_hi + ((size_t)h * S_LEN + qb * 128) * HEAD_DIM;
    const __nv_bfloat16* ql_g = g_q_lo + ((size_t)h * S_LEN + qb * 128) * HEAD_DIM;
    #pragma unroll
    for (int i = 0; i < 8; ++i) {
        int idx = tid + i * 256;
        int row = idx >> 4, cp = idx & 15;
        cp16(smb + FL_QH + row * 272 + cp * 16, qh_g + (size_t)row * HEAD_DIM + cp * 8);
        cp16(smb + FL_QL + row * 272 + cp * 16, ql_g + (size_t)row * HEAD_DIM + cp * 8);
    }
    CP_COMMIT();

    const __nv_bfloat16* kh_g = g_k_hi + (size_t)kvh * S_LEN * HEAD_DIM;
    const __nv_bfloat16* kl_g = g_k_lo + (size_t)kvh * S_LEN * HEAD_DIM;
    const __nv_bfloat16* vh_g = g_vT_hi + (size_t)kvh * HEAD_DIM * S_LEN;
    const __nv_bfloat16* vl_g = g_vT_lo + (size_t)kvh * HEAD_DIM * S_LEN;

    float o[16][4];
    #pragma unroll
    for (int nf = 0; nf < 16; ++nf)
        #pragma unroll
        for (int r = 0; r < 4; ++r) o[nf][r] = 0.f;
    float m0 = -1e30f, m1 = -1e30f, l0 = 0.f, l1 = 0.f;
    const int qr0 = qb * 128 + wid * 16 + (lane >> 2);
    const int qr1 = qr0 + 8;
    const int nblk = 2 * qb + 2;

    for (int blk = 0; blk < nblk; ++blk) {
        const int key0 = blk * 64;
        __syncthreads();   // previous compute finished before overwrite
        #pragma unroll
        for (int i = 0; i < 4; ++i) {
            int idx = tid + i * 256;
            int row = idx >> 4, cp = idx & 15;
            cp16(smb + FL_KH + row * 272 + cp * 16,
                 kh_g + (size_t)(key0 + row) * HEAD_DIM + cp * 8);
            cp16(smb + FL_KL + row * 272 + cp * 16,
                 kl_g + (size_t)(key0 + row) * HEAD_DIM + cp * 8);
            int vrow = idx >> 3, vcp = idx & 7;
            cp16(smb + FL_VH + vrow * 144 + vcp * 16,
                 vh_g + (size_t)vrow * S_LEN + key0 + vcp * 8);
            cp16(smb + FL_VL + vrow * 144 + vcp * 16,
                 vl_g + (size_t)vrow * S_LEN + key0 + vcp * 8);
        }
        CP_COMMIT();
        CP_WAIT0();
        __syncthreads();

        // ---- S = Q @ K^T (3-term split) ----
        float s[8][4];
        #pragma unroll
        for (int nf = 0; nf < 8; ++nf)
            #pragma unroll
            for (int r = 0; r < 4; ++r) s[nf][r] = 0.f;

        #pragma unroll
        for (int ks = 0; ks < 8; ++ks) {
            uint32_t qh[4], ql[4];
            uint32_t qoff = (uint32_t)(wid * 16 + lrow) * 272 + (ks * 16 + lk) * 2;
            ldm4(qh[0], qh[1], qh[2], qh[3], smb + FL_QH + qoff);
            ldm4(ql[0], ql[1], ql[2], ql[3], smb + FL_QL + qoff);
            #pragma unroll
            for (int nf2 = 0; nf2 < 4; ++nf2) {
                uint32_t koff = (uint32_t)(nf2 * 16 + nadd) * 272 + (ks * 16 + kadd) * 2;
                uint32_t kh[4], kl[4];
                ldm4(kh[0], kh[1], kh[2], kh[3], smb + FL_KH + koff);
                ldm4(kl[0], kl[1], kl[2], kl[3], smb + FL_KL + koff);
                mma16816(s[nf2*2],   qh, kh);
                mma16816(s[nf2*2],   qh, kl);
                mma16816(s[nf2*2],   ql, kh);
                mma16816(s[nf2*2+1], qh, kh + 2);
                mma16816(s[nf2*2+1], qh, kl + 2);
                mma16816(s[nf2*2+1], ql, kh + 2);
            }
        }

        // ---- scale + causal mask ----
        if (blk >= 2 * qb) {
            #pragma unroll
            for (int nf = 0; nf < 8; ++nf) {
                int c0 = key0 + 8 * nf + 2 * (lane & 3);
                s[nf][0] = (c0     > qr0) ? -1e30f : s[nf][0] * ATTN_SCALE;
                s[nf][1] = (c0 + 1 > qr0) ? -1e30f : s[nf][1] * ATTN_SCALE;
                s[nf][2] = (c0     > qr1) ? -1e30f : s[nf][2] * ATTN_SCALE;
                s[nf][3] = (c0 + 1 > qr1) ? -1e30f : s[nf][3] * ATTN_SCALE;
            }
        } else {
            #pragma unroll
            for (int nf = 0; nf < 8; ++nf)
                #pragma unroll
                for (int r = 0; r < 4; ++r) s[nf][r] *= ATTN_SCALE;
        }

        // ---- online softmax (rows r, r+8 per thread; quad reduce) ----
        float mx0 = -1e30f, mx1 = -1e30f;
        #pragma unroll
        for (int nf = 0; nf < 8; ++nf) {
            mx0 = fmaxf(mx0, fmaxf(s[nf][0], s[nf][1]));
            mx1 = fmaxf(mx1, fmaxf(s[nf][2], s[nf][3]));
        }
        mx0 = fmaxf(mx0, __shfl_xor_sync(0xffffffffu, mx0, 1));
        mx0 = fmaxf(mx0, __shfl_xor_sync(0xffffffffu, mx0, 2));
        mx1 = fmaxf(mx1, __shfl_xor_sync(0xffffffffu, mx1, 1));
        mx1 = fmaxf(mx1, __shfl_xor_sync(0xffffffffu, mx1, 2));

        float mn0 = fmaxf(m0, mx0), mn1 = fmaxf(m1, mx1);
        float corr0 = __expf(m0 - mn0), corr1 = __expf(m1 - mn1);
        float sum0 = 0.f, sum1 = 0.f;
        #pragma unroll
        for (int nf = 0; nf < 8; ++nf) {
            s[nf][0] = __expf(s[nf][0] - mn0);
            s[nf][1] = __expf(s[nf][1] - mn0);
            s[nf][2] = __expf(s[nf][2] - mn1);
            s[nf][3] = __expf(s[nf][3] - mn1);
            sum0 += s[nf][0] + s[nf][1];
            sum1 += s[nf][2] + s[nf][3];
        }
        sum0 += __shfl_xor_sync(0xffffffffu, sum0, 1);
        sum0 += __shfl_xor_sync(0xffffffffu, sum0, 2);
        sum1 += __shfl_xor_sync(0xffffffffu, sum1, 1);
        sum1 += __shfl_xor_sync(0xffffffffu, sum1, 2);
        l0 = l0 * corr0 + sum0;  m0 = mn0;
        l1 = l1 * corr1 + sum1;  m1 = mn1;

        #pragma unroll
        for (int nf = 0; nf < 16; ++nf) {
            o[nf][0] *= corr0; o[nf][1] *= corr0;
            o[nf][2] *= corr1; o[nf][3] *= corr1;
        }

        // ---- repack P into A fragments (hi/lo) ----
        uint32_t ph[4][4], pl[4][4];
        #pragma unroll
        for (int ks = 0; ks < 4; ++ks) {
            int f0 = 2 * ks, f1 = f0 + 1;
            ph[ks][0] = pack_hilo(s[f0][0], s[f0][1], pl[ks][0]);
            ph[ks][1] = pack_hilo(s[f0][2], s[f0][3], pl[ks][1]);
            ph[ks][2] = pack_hilo(s[f1][0], s[f1][1], pl[ks][2]);
            ph[ks][3] = pack_hilo(s[f1][2], s[f1][3], pl[ks][3]);
        }

        // ---- O += P @ V (3-term split; V^T in smem as [d][kv]) ----
        #pragma unroll
        for (int ks = 0; ks < 4; ++ks) {
            #pragma unroll
            for (int nf2 = 0; nf2 < 8; ++nf2) {
                uint32_t voff = (uint32_t)(nf2 * 16 + nadd) * 144 + (ks * 16 + kadd) * 2;
                uint32_t vh[4], vl[4];
                ldm4(vh[0], vh[1], vh[2], vh[3], smb + FL_VH + voff);
                ldm4(vl[0], vl[1], vl[2], vl[3], smb + FL_VL + voff);
                mma16816(o[nf2*2],   ph[ks], vh);
                mma16816(o[nf2*2],   pl[ks], vh);
                mma16816(o[nf2*2],   ph[ks], vl);
                mma16816(o[nf2*2+1], ph[ks], vh + 2);
                mma16816(o[nf2*2+1], pl[ks], vh + 2);
                mma16816(o[nf2*2+1], ph[ks], vl + 2);
            }
        }
    }

    // ---- epilogue: normalize and write hi/lo bf16 to g_at ----
    float inv0 = 1.f / l0, inv1 = 1.f / l1;
    #pragma unroll
    for (int nf = 0; nf < 16; ++nf) {
        int dcol = 8 * nf + 2 * (lane & 3);
        size_t o0 = (size_t)qr0 * HIDDEN + h * HEAD_DIM + dcol;
        size_t o1 = (size_t)qr1 * HIDDEN + h * HEAD_DIM + dcol;
        uint32_t lo;
        uint32_t hi = pack_hilo(o[nf][0] * inv0, o[nf][1] * inv0, lo);
        *reinterpret_cast<uint32_t*>(g_at_hi + o0) = hi;
        *reinterpret_cast<uint32_t*>(g_at_lo + o0) = lo;
        hi = pack_hilo(o[nf][2] * inv1, o[nf][3] * inv1, lo);
        *reinterpret_cast<uint32_t*>(g_at_hi + o1) = hi;
        *reinterpret_cast<uint32_t*>(g_at_lo + o1) = lo;
    }
}

// ===================== launch ================================================
extern "C" void kernel_launch(void* const* d_in, const int* in_sizes, int n_in,
                              void* d_out, int out_size)
{
    const float* X    = (const float*)d_in[0];
    const float* cosT = (const float*)d_in[1];
    const float* sinT = (const float*)d_in[2];
    const float* Wq   = (const float*)d_in[3];
    const float* bq   = (const float*)d_in[4];
    const float* Wk   = (const float*)d_in[5];
    const float* bk   = (const float*)d_in[6];
    const float* Wv   = (const float*)d_in[7];
    const float* bv   = (const float*)d_in[8];
    const float* Wo   = (const float*)d_in[9];
    float* out = (float*)d_out;

    __nv_bfloat16 *x_hi, *x_lo, *w_hi, *w_lo, *wo_hi, *wo_lo;
    cudaGetSymbolAddress((void**)&x_hi,  g_x_hi);
    cudaGetSymbolAddress((void**)&x_lo,  g_x_lo);
    cudaGetSymbolAddress((void**)&w_hi,  g_w_hi);
    cudaGetSymbolAddress((void**)&w_lo,  g_w_lo);
    cudaGetSymbolAddress((void**)&wo_hi, g_wo_hi);
    cudaGetSymbolAddress((void**)&wo_lo, g_wo_lo);

    cudaFuncSetAttribute(qkv_mma_kernel,  cudaFuncAttributeMaxDynamicSharedMemorySize, GEMM_SMEM);
    cudaFuncSetAttribute(out_mma_kernel,  cudaFuncAttributeMaxDynamicSharedMemorySize, GEMM_SMEM);
    cudaFuncSetAttribute(flash_mma_kernel, cudaFuncAttributeMaxDynamicSharedMemorySize, FLASH_SMEM);

    // 1) convert inputs to bf16 hi/lo
    {
        int n4 = S_LEN * HIDDEN / 4;
        cvt_split_kernel<<<(n4 + 255) / 256, 256>>>(X, x_hi, x_lo, n4);
    }
    {
        int n4 = (N_HEADS * HEAD_DIM) * HIDDEN / 4;
        cvt_split_kernel<<<(n4 + 255) / 256, 256>>>(Wq, w_hi, w_lo, n4);
        int off = N_HEADS * HEAD_DIM * HIDDEN;
        int m4 = (N_KV * HEAD_DIM) * HIDDEN / 4;
        cvt_split_kernel<<<(m4 + 255) / 256, 256>>>(Wk, w_hi + off, w_lo + off, m4);
        off += N_KV * HEAD_DIM * HIDDEN;
        cvt_split_kernel<<<(m4 + 255) / 256, 256>>>(Wv, w_hi + off, w_lo + off, m4);
    }
    {
        int n4 = HIDDEN * HIDDEN / 4;
        cvt_split_kernel<<<(n4 + 255) / 256, 256>>>(Wo, wo_hi, wo_lo, n4);
    }

    // 2) QKV projection (mma.sync tensor cores)
    qkv_mma_kernel<<<dim3(16, 36), 256, GEMM_SMEM>>>(bq, bk, bv);

    // 3) RoPE -> bf16 hi/lo; V transpose -> bf16 hi/lo
    {
        int n = (N_HEADS + N_KV) * S_LEN * 64;
        rope_cvt_kernel<<<(n + 255) / 256, 256>>>(cosT, sinT);
    }
    {
        int n = N_KV * S_LEN * HEAD_DIM;
        v_cvt_kernel<<<(n + 255) / 256, 256>>>();
    }

    // 4) flash attention (mma.sync, hi/lo split)
    flash_mma_kernel<<<dim3(16, N_HEADS), 256, FLASH_SMEM>>>();

    // 5) output projection
    out_mma_kernel<<<dim3(16, 28), 256, GEMM_SMEM>>>(out);
}

// round 6
// speedup vs baseline: 3.2164x; 1.0192x over previous
#include <cuda_runtime.h>
#include <cuda_bf16.h>
#include <cstdint>

#define S_LEN 2048
#define HIDDEN 3584
#define N_HEADS 28
#define N_KV 4
#define HEAD_DIM 128
#define GROUPS 7
#define QKV_N (N_HEADS * HEAD_DIM + 2 * N_KV * HEAD_DIM)   // 4608
#define ATTN_SCALE 0.08838834764831845f

// ===================== device scratch ========================================
__device__ float g_q[N_HEADS * S_LEN * HEAD_DIM];
__device__ float g_k[N_KV * S_LEN * HEAD_DIM];
__device__ float g_v[N_KV * S_LEN * HEAD_DIM];

__device__ __nv_bfloat16 g_x_hi[S_LEN * HIDDEN];
__device__ __nv_bfloat16 g_x_lo[S_LEN * HIDDEN];
__device__ __nv_bfloat16 g_w_hi[QKV_N * HIDDEN];
__device__ __nv_bfloat16 g_w_lo[QKV_N * HIDDEN];
__device__ __nv_bfloat16 g_wo_hi[HIDDEN * HIDDEN];
__device__ __nv_bfloat16 g_wo_lo[HIDDEN * HIDDEN];
__device__ __nv_bfloat16 g_at_hi[S_LEN * HIDDEN];
__device__ __nv_bfloat16 g_at_lo[S_LEN * HIDDEN];

__device__ __nv_bfloat16 g_q_hi[N_HEADS * S_LEN * HEAD_DIM];
__device__ __nv_bfloat16 g_q_lo[N_HEADS * S_LEN * HEAD_DIM];
__device__ __nv_bfloat16 g_k_hi[N_KV * S_LEN * HEAD_DIM];
__device__ __nv_bfloat16 g_k_lo[N_KV * S_LEN * HEAD_DIM];
__device__ __nv_bfloat16 g_vT_hi[N_KV * HEAD_DIM * S_LEN];   // [kv][d][s]
__device__ __nv_bfloat16 g_vT_lo[N_KV * HEAD_DIM * S_LEN];

// ===================== low-level helpers =====================================
__device__ __forceinline__ uint32_t smem_u32(const void* p) {
    uint32_t a;
    asm("{ .reg .u64 t; cvta.to.shared.u64 t, %1; cvt.u32.u64 %0, t; }"
        : "=r"(a) : "l"(p));
    return a;
}
__device__ __forceinline__ void cp16(uint32_t s, const void* g) {
    asm volatile("cp.async.cg.shared.global [%0], [%1], 16;" :: "r"(s), "l"(g));
}
#define CP_COMMIT() asm volatile("cp.async.commit_group;" ::: "memory")
#define CP_WAIT1()  asm volatile("cp.async.wait_group 1;" ::: "memory")
#define CP_WAIT0()  asm volatile("cp.async.wait_group 0;" ::: "memory")

__device__ __forceinline__ void ldm4(uint32_t& r0, uint32_t& r1, uint32_t& r2,
                                     uint32_t& r3, uint32_t a) {
    asm volatile("ldmatrix.sync.aligned.m8n8.x4.shared.b16 {%0,%1,%2,%3}, [%4];"
        : "=r"(r0), "=r"(r1), "=r"(r2), "=r"(r3) : "r"(a));
}
__device__ __forceinline__ void mma16816(float* c, const uint32_t* a,
                                         const uint32_t* b) {
    asm volatile(
        "mma.sync.aligned.m16n8k16.row.col.f32.bf16.bf16.f32 "
        "{%0,%1,%2,%3}, {%4,%5,%6,%7}, {%8,%9}, {%0,%1,%2,%3};"
        : "+f"(c[0]), "+f"(c[1]), "+f"(c[2]), "+f"(c[3])
        : "r"(a[0]), "r"(a[1]), "r"(a[2]), "r"(a[3]), "r"(b[0]), "r"(b[1]));
}

__device__ __forceinline__ uint32_t pack_hilo(float x, float y, uint32_t& lo) {
    __nv_bfloat16 hx = __float2bfloat16(x);
    __nv_bfloat16 hy = __float2bfloat16(y);
    __nv_bfloat16 lx = __float2bfloat16(x - __bfloat162float(hx));
    __nv_bfloat16 ly = __float2bfloat16(y - __bfloat162float(hy));
    lo = (uint32_t)__bfloat16_as_ushort(lx) | ((uint32_t)__bfloat16_as_ushort(ly) << 16);
    return (uint32_t)__bfloat16_as_ushort(hx) | ((uint32_t)__bfloat16_as_ushort(hy) << 16);
}

// ===================== mma.sync GEMM core (256x128 tile) =====================
// C[m0:+256, n0:+128] = A[m0:+256,:K] @ B[n0:+128,:K]^T; bf16 hi/lo 3-term split.
// 8 warps: warp_m = wid&3 (64-row tiles), warp_n = wid>>2 (64-col tiles).
#define ROW_STRIDE_B 80                    // 32 bf16 (64B) + 16B pad
#define A_MAT 20480                        // 256 * 80
#define B_MAT 10240                        // 128 * 80
#define STAGE_BYTES (2 * A_MAT + 2 * B_MAT)   // 61440
#define GEMM_SMEM (3 * STAGE_BYTES)           // 184320

__device__ __forceinline__ void load_stage(
    const __nv_bfloat16* a_hi, const __nv_bfloat16* a_lo,
    const __nv_bfloat16* b_hi, const __nv_bfloat16* b_lo,
    int K, int kb, uint32_t sbase, int tid)
{
    // A: 256 rows x 64B x 2 mats = 2048 cp16;  B: 128 rows x 64B x 2 = 1024 cp16
    #pragma unroll
    for (int i = 0; i < 8; ++i) {
        int idx = tid + i * 256;           // 0..2047
        int mat = idx >> 10;               // 0 = Ah, 1 = Al
        int rem = idx & 1023;
        int row = rem >> 2;
        int cp  = rem & 3;
        const __nv_bfloat16* src = (mat ? a_lo : a_hi) + (size_t)row * K + kb + cp * 8;
        cp16(sbase + mat * A_MAT + row * ROW_STRIDE_B + cp * 16, src);
    }
    #pragma unroll
    for (int i = 0; i < 4; ++i) {
        int idx = tid + i * 256;           // 0..1023
        int mat = idx >> 9;                // 0 = Bh, 1 = Bl
        int rem = idx & 511;
        int row = rem >> 2;
        int cp  = rem & 3;
        const __nv_bfloat16* src = (mat ? b_lo : b_hi) + (size_t)row * K + kb + cp * 8;
        cp16(sbase + 2 * A_MAT + mat * B_MAT + row * ROW_STRIDE_B + cp * 16, src);
    }
}

__device__ __forceinline__ void compute_stage(
    uint32_t sbase, int warp_m, int warp_n, int lane, float acc[4][8][4])
{
    const uint32_t ahB = sbase;
    const uint32_t alB = sbase + A_MAT;
    const uint32_t bhB = sbase + 2 * A_MAT;
    const uint32_t blB = sbase + 2 * A_MAT + B_MAT;

    const int lrow = lane & 15;
    const int lk   = (lane >> 4) * 8;
    const int g    = lane >> 3;
    const int nadd = ((g >> 1) << 3) + (lane & 7);
    const int kadd = (g & 1) * 8;

    #pragma unroll
    for (int ks = 0; ks < 2; ++ks) {
        uint32_t ah[4][4], al[4][4];
        #pragma unroll
        for (int mf = 0; mf < 4; ++mf) {
            uint32_t off = (uint32_t)(warp_m * 64 + mf * 16 + lrow) * ROW_STRIDE_B
                         + (ks * 16 + lk) * 2;
            ldm4(ah[mf][0], ah[mf][1], ah[mf][2], ah[mf][3], ahB + off);
            ldm4(al[mf][0], al[mf][1], al[mf][2], al[mf][3], alB + off);
        }
        #pragma unroll
        for (int nf2 = 0; nf2 < 4; ++nf2) {
            uint32_t off = (uint32_t)(warp_n * 64 + nf2 * 16 + nadd) * ROW_STRIDE_B
                         + (ks * 16 + kadd) * 2;
            uint32_t bh[4], bl[4];
            ldm4(bh[0], bh[1], bh[2], bh[3], bhB + off);
            ldm4(bl[0], bl[1], bl[2], bl[3], blB + off);
            #pragma unroll
            for (int mf = 0; mf < 4; ++mf) {
                mma16816(acc[mf][nf2*2],   ah[mf], bh);
                mma16816(acc[mf][nf2*2],   ah[mf], bl);
                mma16816(acc[mf][nf2*2],   al[mf], bh);
                mma16816(acc[mf][nf2*2+1], ah[mf], bh + 2);
                mma16816(acc[mf][nf2*2+1], ah[mf], bl + 2);
                mma16816(acc[mf][nf2*2+1], al[mf], bh + 2);
            }
        }
    }
}

__device__ __forceinline__ void gemm_main(
    const __nv_bfloat16* ahi, const __nv_bfloat16* alo,
    const __nv_bfloat16* bhi, const __nv_bfloat16* blo,
    int K, char* sm, float acc[4][8][4])
{
    const int tid = threadIdx.x;
    const int wid = tid >> 5;
    const int lane = tid & 31;
    const int warp_m = wid & 3;
    const int warp_n = wid >> 2;
    const uint32_t smb = smem_u32(sm);

    #pragma unroll
    for (int mf = 0; mf < 4; ++mf)
        #pragma unroll
        for (int nf = 0; nf < 8; ++nf)
            #pragma unroll
            for (int r = 0; r < 4; ++r) acc[mf][nf][r] = 0.f;

    const int nIters = K / 32;
    load_stage(ahi, alo, bhi, blo, K, 0, smb, tid);
    CP_COMMIT();
    load_stage(ahi, alo, bhi, blo, K, 32, smb + STAGE_BYTES, tid);
    CP_COMMIT();

    for (int c = 0; c < nIters; ++c) {
        CP_WAIT1();
        __syncthreads();
        compute_stage(smb + (c % 3) * STAGE_BYTES, warp_m, warp_n, lane, acc);
        __syncthreads();
        if (c + 2 < nIters)
            load_stage(ahi, alo, bhi, blo, K, (c + 2) * 32,
                       smb + ((c + 2) % 3) * STAGE_BYTES, tid);
        CP_COMMIT();
    }
    CP_WAIT0();
}

// ===================== QKV projection =======================================
__global__ __launch_bounds__(256, 1)
void qkv_mma_kernel(const float* __restrict__ bq, const float* __restrict__ bk,
                    const float* __restrict__ bv)
{
    extern __shared__ __align__(128) char sm[];
    const int m0 = blockIdx.x * 256;
    const int n0 = blockIdx.y * 128;

    float acc[4][8][4];
    gemm_main(g_x_hi + (size_t)m0 * HIDDEN,
              g_x_lo + (size_t)m0 * HIDDEN,
              g_w_hi + (size_t)n0 * HIDDEN,
              g_w_lo + (size_t)n0 * HIDDEN,
              HIDDEN, sm, acc);

    float* dst;
    const float* bias;
    if (n0 < N_HEADS * HEAD_DIM) {
        dst = g_q + (size_t)(n0 >> 7) * S_LEN * HEAD_DIM; bias = bq + n0;
    } else if (n0 < (N_HEADS + N_KV) * HEAD_DIM) {
        int o = n0 - N_HEADS * HEAD_DIM;
        dst = g_k + (size_t)(o >> 7) * S_LEN * HEAD_DIM; bias = bk + o;
    } else {
        int o = n0 - (N_HEADS + N_KV) * HEAD_DIM;
        dst = g_v + (size_t)(o >> 7) * S_LEN * HEAD_DIM; bias = bv + o;
    }

    const int tid = threadIdx.x;
    const int wid = tid >> 5;
    const int lane = tid & 31;
    const int warp_m = wid & 3;
    const int warp_n = wid >> 2;

    #pragma unroll
    for (int mf = 0; mf < 4; ++mf) {
        int row = m0 + warp_m * 64 + mf * 16 + (lane >> 2);
        #pragma unroll
        for (int nf = 0; nf < 8; ++nf) {
            int col = warp_n * 64 + nf * 8 + (lane & 3) * 2;   // 0..127
            float b0 = bias[col], b1 = bias[col + 1];
            dst[(size_t)row * HEAD_DIM + col]           = acc[mf][nf][0] + b0;
            dst[(size_t)row * HEAD_DIM + col + 1]       = acc[mf][nf][1] + b1;
            dst[(size_t)(row + 8) * HEAD_DIM + col]     = acc[mf][nf][2] + b0;
            dst[(size_t)(row + 8) * HEAD_DIM + col + 1] = acc[mf][nf][3] + b1;
        }
    }
}

// ===================== output projection ====================================
__global__ __launch_bounds__(256, 1)
void out_mma_kernel(float* __restrict__ out)
{
    extern __shared__ __align__(128) char sm[];
    const int m0 = blockIdx.x * 256;
    const int n0 = blockIdx.y * 128;

    float acc[4][8][4];
    gemm_main(g_at_hi + (size_t)m0 * HIDDEN,
              g_at_lo + (size_t)m0 * HIDDEN,
              g_wo_hi + (size_t)n0 * HIDDEN,
              g_wo_lo + (size_t)n0 * HIDDEN,
              HIDDEN, sm, acc);

    const int tid = threadIdx.x;
    const int wid = tid >> 5;
    const int lane = tid & 31;
    const int warp_m = wid & 3;
    const int warp_n = wid >> 2;

    #pragma unroll
    for (int mf = 0; mf < 4; ++mf) {
        int row = m0 + warp_m * 64 + mf * 16 + (lane >> 2);
        #pragma unroll
        for (int nf = 0; nf < 8; ++nf) {
            int col = n0 + warp_n * 64 + nf * 8 + (lane & 3) * 2;
            out[(size_t)row * HIDDEN + col]           = acc[mf][nf][0];
            out[(size_t)row * HIDDEN + col + 1]       = acc[mf][nf][1];
            out[(size_t)(row + 8) * HIDDEN + col]     = acc[mf][nf][2];
            out[(size_t)(row + 8) * HIDDEN + col + 1] = acc[mf][nf][3];
        }
    }
}

// ===================== fp32 -> bf16 hi/lo split ==============================
__global__ void cvt_split_kernel(const float* __restrict__ src,
                                 __nv_bfloat16* __restrict__ hi,
                                 __nv_bfloat16* __restrict__ lo, int n4)
{
    int i = blockIdx.x * blockDim.x + threadIdx.x;
    if (i >= n4) return;
    float4 v = reinterpret_cast<const float4*>(src)[i];
    __nv_bfloat16 h0 = __float2bfloat16(v.x);
    __nv_bfloat16 h1 = __float2bfloat16(v.y);
    __nv_bfloat16 h2 = __float2bfloat16(v.z);
    __nv_bfloat16 h3 = __float2bfloat16(v.w);
    __nv_bfloat16 l0 = __float2bfloat16(v.x - __bfloat162float(h0));
    __nv_bfloat16 l1 = __float2bfloat16(v.y - __bfloat162float(h1));
    __nv_bfloat16 l2 = __float2bfloat16(v.z - __bfloat162float(h2));
    __nv_bfloat16 l3 = __float2bfloat16(v.w - __bfloat162float(h3));
    ushort4 hv, lv;
    hv.x = __bfloat16_as_ushort(h0); hv.y = __bfloat16_as_ushort(h1);
    hv.z = __bfloat16_as_ushort(h2); hv.w = __bfloat16_as_ushort(h3);
    lv.x = __bfloat16_as_ushort(l0); lv.y = __bfloat16_as_ushort(l1);
    lv.z = __bfloat16_as_ushort(l2); lv.w = __bfloat16_as_ushort(l3);
    reinterpret_cast<ushort4*>(hi)[i] = hv;
    reinterpret_cast<ushort4*>(lo)[i] = lv;
}

// ===================== RoPE + convert to hi/lo bf16 ==========================
__global__ void rope_cvt_kernel(const float* __restrict__ cos_t,
                                const float* __restrict__ sin_t)
{
    int idx = blockIdx.x * blockDim.x + threadIdx.x;
    if (idx >= (N_HEADS + N_KV) * S_LEN * 64) return;
    int d = idx & 63;
    int s = (idx >> 6) & (S_LEN - 1);
    int head = idx >> 17;

    const float* p;
    __nv_bfloat16 *hi, *lo;
    size_t base;
    if (head < N_HEADS) {
        base = (size_t)head * S_LEN * HEAD_DIM;
        p = g_q + base; hi = g_q_hi + base; lo = g_q_lo + base;
    } else {
        base = (size_t)(head - N_HEADS) * S_LEN * HEAD_DIM;
        p = g_k + base; hi = g_k_hi + base; lo = g_k_lo + base;
    }
    float c  = cos_t[s * HEAD_DIM + d];
    float sn = sin_t[s * HEAD_DIM + d];
    float x1 = p[(size_t)s * HEAD_DIM + d];
    float x2 = p[(size_t)s * HEAD_DIM + d + 64];
    float y1 = x1 * c - x2 * sn;
    float y2 = x2 * c + x1 * sn;
    __nv_bfloat16 h1 = __float2bfloat16(y1);
    __nv_bfloat16 h2 = __float2bfloat16(y2);
    size_t o1 = (size_t)s * HEAD_DIM + d;
    size_t o2 = o1 + 64;
    hi[o1] = h1; lo[o1] = __float2bfloat16(y1 - __bfloat162float(h1));
    hi[o2] = h2; lo[o2] = __float2bfloat16(y2 - __bfloat162float(h2));
}

// ===================== V transpose + convert =================================
__global__ void v_cvt_kernel()
{
    int idx = blockIdx.x * blockDim.x + threadIdx.x;
    if (idx >= N_KV * S_LEN * HEAD_DIM) return;
    int kv = idx >> 18;
    int rem = idx & (S_LEN * HEAD_DIM - 1);
    int s = rem >> 7;
    int d = rem & 127;
    float v = g_v[idx];
    __nv_bfloat16 h = __float2bfloat16(v);
    size_t o = (size_t)kv * HEAD_DIM * S_LEN + (size_t)d * S_LEN + s;
    g_vT_hi[o] = h;
    g_vT_lo[o] = __float2bfloat16(v - __bfloat162float(h));
}

// ===================== flash attention (mma.sync, hi/lo split) ===============
#define FL_QH 0u
#define FL_QL 34816u
#define FL_KH 69632u
#define FL_KL 87040u
#define FL_VH 104448u
#define FL_VL 122880u
#define FLASH_SMEM 141312

__global__ __launch_bounds__(256, 1)
void flash_mma_kernel()
{
    extern __shared__ __align__(128) char sm[];
    const uint32_t smb = smem_u32(sm);
    const int qb  = 15 - (int)blockIdx.x;      // big tiles first
    const int h   = blockIdx.y;
    const int kvh = h / GROUPS;
    const int tid = threadIdx.x;
    const int wid = tid >> 5;
    const int lane = tid & 31;
    const int lrow = lane & 15;
    const int lk   = (lane >> 4) * 8;
    const int g    = lane >> 3;
    const int nadd = ((g >> 1) << 3) + (lane & 7);
    const int kadd = (g & 1) * 8;

    const __nv_bfloat16* qh_g = g_q_hi + ((size_t)h * S_LEN + qb * 128) * HEAD_DIM;
    const __nv_bfloat16* ql_g = g_q_lo + ((size_t)h * S_LEN + qb * 128) * HEAD_DIM;
    #pragma unroll
    for (int i = 0; i < 8; ++i) {
        int idx = tid + i * 256;
        int row = idx >> 4, cp = idx & 15;
        cp16(smb + FL_QH + row * 272 + cp * 16, qh_g + (size_t)row * HEAD_DIM + cp * 8);
        cp16(smb + FL_QL + row * 272 + cp * 16, ql_g + (size_t)row * HEAD_DIM + cp * 8);
    }
    CP_COMMIT();

    const __nv_bfloat16* kh_g = g_k_hi + (size_t)kvh * S_LEN * HEAD_DIM;
    const __nv_bfloat16* kl_g = g_k_lo + (size_t)kvh * S_LEN * HEAD_DIM;
    const __nv_bfloat16* vh_g = g_vT_hi + (size_t)kvh * HEAD_DIM * S_LEN;
    const __nv_bfloat16* vl_g = g_vT_lo + (size_t)kvh * HEAD_DIM * S_LEN;

    float o[16][4];
    #pragma unroll
    for (int nf = 0; nf < 16; ++nf)
        #pragma unroll
        for (int r = 0; r < 4; ++r) o[nf][r] = 0.f;
    float m0 = -1e30f, m1 = -1e30f, l0 = 0.f, l1 = 0.f;
    const int qr0 = qb * 128 + wid * 16 + (lane >> 2);
    const int qr1 = qr0 + 8;
    const int nblk = 2 * qb + 2;

    for (int blk = 0; blk < nblk; ++blk) {
        const int key0 = blk * 64;
        __syncthreads();
        #pragma unroll
        for (int i = 0; i < 4; ++i) {
            int idx = tid + i * 256;
            int row = idx >> 4, cp = idx & 15;
            cp16(smb + FL_KH + row * 272 + cp * 16,
                 kh_g + (size_t)(key0 + row) * HEAD_DIM + cp * 8);
            cp16(smb + FL_KL + row * 272 + cp * 16,
                 kl_g + (size_t)(key0 + row) * HEAD_DIM + cp * 8);
            int vrow = idx >> 3, vcp = idx & 7;
            cp16(smb + FL_VH + vrow * 144 + vcp * 16,
                 vh_g + (size_t)vrow * S_LEN + key0 + vcp * 8);
            cp16(smb + FL_VL + vrow * 144 + vcp * 16,
                 vl_g + (size_t)vrow * S_LEN + key0 + vcp * 8);
        }
        CP_COMMIT();
        CP_WAIT0();
        __syncthreads();

        float s[8][4];
        #pragma unroll
        for (int nf = 0; nf < 8; ++nf)
            #pragma unroll
            for (int r = 0; r < 4; ++r) s[nf][r] = 0.f;

        #pragma unroll
        for (int ks = 0; ks < 8; ++ks) {
            uint32_t qh[4], ql[4];
            uint32_t qoff = (uint32_t)(wid * 16 + lrow) * 272 + (ks * 16 + lk) * 2;
            ldm4(qh[0], qh[1], qh[2], qh[3], smb + FL_QH + qoff);
            ldm4(ql[0], ql[1], ql[2], ql[3], smb + FL_QL + qoff);
            #pragma unroll
            for (int nf2 = 0; nf2 < 4; ++nf2) {
                uint32_t koff = (uint32_t)(nf2 * 16 + nadd) * 272 + (ks * 16 + kadd) * 2;
                uint32_t kh[4], kl[4];
                ldm4(kh[0], kh[1], kh[2], kh[3], smb + FL_KH + koff);
                ldm4(kl[0], kl[1], kl[2], kl[3], smb + FL_KL + koff);
                mma16816(s[nf2*2],   qh, kh);
                mma16816(s[nf2*2],   qh, kl);
                mma16816(s[nf2*2],   ql, kh);
                mma16816(s[nf2*2+1], qh, kh + 2);
                mma16816(s[nf2*2+1], qh, kl + 2);
                mma16816(s[nf2*2+1], ql, kh + 2);
            }
        }

        if (blk >= 2 * qb) {
            #pragma unroll
            for (int nf = 0; nf < 8; ++nf) {
                int c0 = key0 + 8 * nf + 2 * (lane & 3);
                s[nf][0] = (c0     > qr0) ? -1e30f : s[nf][0] * ATTN_SCALE;
                s[nf][1] = (c0 + 1 > qr0) ? -1e30f : s[nf][1] * ATTN_SCALE;
                s[nf][2] = (c0     > qr1) ? -1e30f : s[nf][2] * ATTN_SCALE;
                s[nf][3] = (c0 + 1 > qr1) ? -1e30f : s[nf][3] * ATTN_SCALE;
            }
        } else {
            #pragma unroll
            for (int nf = 0; nf < 8; ++nf)
                #pragma unroll
                for (int r = 0; r < 4; ++r) s[nf][r] *= ATTN_SCALE;
        }

        float mx0 = -1e30f, mx1 = -1e30f;
        #pragma unroll
        for (int nf = 0; nf < 8; ++nf) {
            mx0 = fmaxf(mx0, fmaxf(s[nf][0], s[nf][1]));
            mx1 = fmaxf(mx1, fmaxf(s[nf][2], s[nf][3]));
        }
        mx0 = fmaxf(mx0, __shfl_xor_sync(0xffffffffu, mx0, 1));
        mx0 = fmaxf(mx0, __shfl_xor_sync(0xffffffffu, mx0, 2));
        mx1 = fmaxf(mx1, __shfl_xor_sync(0xffffffffu, mx1, 1));
        mx1 = fmaxf(mx1, __shfl_xor_sync(0xffffffffu, mx1, 2));

        float mn0 = fmaxf(m0, mx0), mn1 = fmaxf(m1, mx1);
        float corr0 = __expf(m0 - mn0), corr1 = __expf(m1 - mn1);
        float sum0 = 0.f, sum1 = 0.f;
        #pragma unroll
        for (int nf = 0; nf < 8; ++nf) {
            s[nf][0] = __expf(s[nf][0] - mn0);
            s[nf][1] = __expf(s[nf][1] - mn0);
            s[nf][2] = __expf(s[nf][2] - mn1);
            s[nf][3] = __expf(s[nf][3] - mn1);
            sum0 += s[nf][0] + s[nf][1];
            sum1 += s[nf][2] + s[nf][3];
        }
        sum0 += __shfl_xor_sync(0xffffffffu, sum0, 1);
        sum0 += __shfl_xor_sync(0xffffffffu, sum0, 2);
        sum1 += __shfl_xor_sync(0xffffffffu, sum1, 1);
        sum1 += __shfl_xor_sync(0xffffffffu, sum1, 2);
        l0 = l0 * corr0 + sum0;  m0 = mn0;
        l1 = l1 * corr1 + sum1;  m1 = mn1;

        #pragma unroll
        for (int nf = 0; nf < 16; ++nf) {
            o[nf][0] *= corr0; o[nf][1] *= corr0;
            o[nf][2] *= corr1; o[nf][3] *= corr1;
        }

        uint32_t ph[4][4], pl[4][4];
        #pragma unroll
        for (int ks = 0; ks < 4; ++ks) {
            int f0 = 2 * ks, f1 = f0 + 1;
            ph[ks][0] = pack_hilo(s[f0][0], s[f0][1], pl[ks][0]);
            ph[ks][1] = pack_hilo(s[f0][2], s[f0][3], pl[ks][1]);
            ph[ks][2] = pack_hilo(s[f1][0], s[f1][1], pl[ks][2]);
            ph[ks][3] = pack_hilo(s[f1][2], s[f1][3], pl[ks][3]);
        }

        #pragma unroll
        for (int ks = 0; ks < 4; ++ks) {
            #pragma unroll
            for (int nf2 = 0; nf2 < 8; ++nf2) {
                uint32_t voff = (uint32_t)(nf2 * 16 + nadd) * 144 + (ks * 16 + kadd) * 2;
                uint32_t vh[4], vl[4];
                ldm4(vh[0], vh[1], vh[2], vh[3], smb + FL_VH + voff);
                ldm4(vl[0], vl[1], vl[2], vl[3], smb + FL_VL + voff);
                mma16816(o[nf2*2],   ph[ks], vh);
                mma16816(o[nf2*2],   pl[ks], vh);
                mma16816(o[nf2*2],   ph[ks], vl);
                mma16816(o[nf2*2+1], ph[ks], vh + 2);
                mma16816(o[nf2*2+1], pl[ks], vh + 2);
                mma16816(o[nf2*2+1], ph[ks], vl + 2);
            }
        }
    }

    float inv0 = 1.f / l0, inv1 = 1.f / l1;
    #pragma unroll
    for (int nf = 0; nf < 16; ++nf) {
        int dcol = 8 * nf + 2 * (lane & 3);
        size_t o0 = (size_t)qr0 * HIDDEN + h * HEAD_DIM + dcol;
        size_t o1 = (size_t)qr1 * HIDDEN + h * HEAD_DIM + dcol;
        uint32_t lo;
        uint32_t hi = pack_hilo(o[nf][0] * inv0, o[nf][1] * inv0, lo);
        *reinterpret_cast<uint32_t*>(g_at_hi + o0) = hi;
        *reinterpret_cast<uint32_t*>(g_at_lo + o0) = lo;
        hi = pack_hilo(o[nf][2] * inv1, o[nf][3] * inv1, lo);
        *reinterpret_cast<uint32_t*>(g_at_hi + o1) = hi;
        *reinterpret_cast<uint32_t*>(g_at_lo + o1) = lo;
    }
}

// ===================== launch ================================================
extern "C" void kernel_launch(void* const* d_in, const int* in_sizes, int n_in,
                              void* d_out, int out_size)
{
    const float* X    = (const float*)d_in[0];
    const float* cosT = (const float*)d_in[1];
    const float* sinT = (const float*)d_in[2];
    const float* Wq   = (const float*)d_in[3];
    const float* bq   = (const float*)d_in[4];
    const float* Wk   = (const float*)d_in[5];
    const float* bk   = (const float*)d_in[6];
    const float* Wv   = (const float*)d_in[7];
    const float* bv   = (const float*)d_in[8];
    const float* Wo   = (const float*)d_in[9];
    float* out = (float*)d_out;

    __nv_bfloat16 *x_hi, *x_lo, *w_hi, *w_lo, *wo_hi, *wo_lo;
    cudaGetSymbolAddress((void**)&x_hi,  g_x_hi);
    cudaGetSymbolAddress((void**)&x_lo,  g_x_lo);
    cudaGetSymbolAddress((void**)&w_hi,  g_w_hi);
    cudaGetSymbolAddress((void**)&w_lo,  g_w_lo);
    cudaGetSymbolAddress((void**)&wo_hi, g_wo_hi);
    cudaGetSymbolAddress((void**)&wo_lo, g_wo_lo);

    cudaFuncSetAttribute(qkv_mma_kernel,  cudaFuncAttributeMaxDynamicSharedMemorySize, GEMM_SMEM);
    cudaFuncSetAttribute(out_mma_kernel,  cudaFuncAttributeMaxDynamicSharedMemorySize, GEMM_SMEM);
    cudaFuncSetAttribute(flash_mma_kernel, cudaFuncAttributeMaxDynamicSharedMemorySize, FLASH_SMEM);

    // 1) convert inputs to bf16 hi/lo
    {
        int n4 = S_LEN * HIDDEN / 4;
        cvt_split_kernel<<<(n4 + 255) / 256, 256>>>(X, x_hi, x_lo, n4);
    }
    {
        int n4 = (N_HEADS * HEAD_DIM) * HIDDEN / 4;
        cvt_split_kernel<<<(n4 + 255) / 256, 256>>>(Wq, w_hi, w_lo, n4);
        int off = N_HEADS * HEAD_DIM * HIDDEN;
        int m4 = (N_KV * HEAD_DIM) * HIDDEN / 4;
        cvt_split_kernel<<<(m4 + 255) / 256, 256>>>(Wk, w_hi + off, w_lo + off, m4);
        off += N_KV * HEAD_DIM * HIDDEN;
        cvt_split_kernel<<<(m4 + 255) / 256, 256>>>(Wv, w_hi + off, w_lo + off, m4);
    }
    {
        int n4 = HIDDEN * HIDDEN / 4;
        cvt_split_kernel<<<(n4 + 255) / 256, 256>>>(Wo, wo_hi, wo_lo, n4);
    }

    // 2) QKV projection (256x128 tiles)
    qkv_mma_kernel<<<dim3(8, 36), 256, GEMM_SMEM>>>(bq, bk, bv);

    // 3) RoPE -> bf16 hi/lo; V transpose -> bf16 hi/lo
    {
        int n = (N_HEADS + N_KV) * S_LEN * 64;
        rope_cvt_kernel<<<(n + 255) / 256, 256>>>(cosT, sinT);
    }
    {
        int n = N_KV * S_LEN * HEAD_DIM;
        v_cvt_kernel<<<(n + 255) / 256, 256>>>();
    }

    // 4) flash attention (mma.sync, hi/lo split)
    flash_mma_kernel<<<dim3(16, N_HEADS), 256, FLASH_SMEM>>>();

    // 5) output projection (256x128 tiles)
    out_mma_kernel<<<dim3(8, 28), 256, GEMM_SMEM>>>(out);
}

// round 7
// speedup vs baseline: 3.4844x; 1.0833x over previous
#include <cuda_runtime.h>
#include <cuda_bf16.h>
#include <cstdint>

#define S_LEN 2048
#define HIDDEN 3584
#define N_HEADS 28
#define N_KV 4
#define HEAD_DIM 128
#define GROUPS 7
#define QKV_N (N_HEADS * HEAD_DIM + 2 * N_KV * HEAD_DIM)   // 4608
#define ATTN_SCALE 0.08838834764831845f

// ===================== device scratch ========================================
__device__ float g_q[N_HEADS * S_LEN * HEAD_DIM];
__device__ float g_k[N_KV * S_LEN * HEAD_DIM];
__device__ float g_v[N_KV * S_LEN * HEAD_DIM];

__device__ __nv_bfloat16 g_x_hi[S_LEN * HIDDEN];
__device__ __nv_bfloat16 g_x_lo[S_LEN * HIDDEN];
__device__ __nv_bfloat16 g_w_hi[QKV_N * HIDDEN];
__device__ __nv_bfloat16 g_w_lo[QKV_N * HIDDEN];
__device__ __nv_bfloat16 g_wo_hi[HIDDEN * HIDDEN];
__device__ __nv_bfloat16 g_wo_lo[HIDDEN * HIDDEN];
__device__ __nv_bfloat16 g_at_hi[S_LEN * HIDDEN];
__device__ __nv_bfloat16 g_at_lo[S_LEN * HIDDEN];

__device__ __nv_bfloat16 g_q_hi[N_HEADS * S_LEN * HEAD_DIM];
__device__ __nv_bfloat16 g_q_lo[N_HEADS * S_LEN * HEAD_DIM];
__device__ __nv_bfloat16 g_k_hi[N_KV * S_LEN * HEAD_DIM];
__device__ __nv_bfloat16 g_k_lo[N_KV * S_LEN * HEAD_DIM];
__device__ __nv_bfloat16 g_vT_hi[N_KV * HEAD_DIM * S_LEN];   // [kv][d][s]
__device__ __nv_bfloat16 g_vT_lo[N_KV * HEAD_DIM * S_LEN];

// ===================== low-level helpers =====================================
__device__ __forceinline__ uint32_t smem_u32(const void* p) {
    uint32_t a;
    asm("{ .reg .u64 t; cvta.to.shared.u64 t, %1; cvt.u32.u64 %0, t; }"
        : "=r"(a) : "l"(p));
    return a;
}
__device__ __forceinline__ void cp16(uint32_t s, const void* g) {
    asm volatile("cp.async.cg.shared.global [%0], [%1], 16;" :: "r"(s), "l"(g));
}
#define CP_COMMIT() asm volatile("cp.async.commit_group;" ::: "memory")
#define CP_WAIT1()  asm volatile("cp.async.wait_group 1;" ::: "memory")
#define CP_WAIT0()  asm volatile("cp.async.wait_group 0;" ::: "memory")

__device__ __forceinline__ void ldm4(uint32_t& r0, uint32_t& r1, uint32_t& r2,
                                     uint32_t& r3, uint32_t a) {
    asm volatile("ldmatrix.sync.aligned.m8n8.x4.shared.b16 {%0,%1,%2,%3}, [%4];"
        : "=r"(r0), "=r"(r1), "=r"(r2), "=r"(r3) : "r"(a));
}
__device__ __forceinline__ void mma16816(float* c, const uint32_t* a,
                                         const uint32_t* b) {
    asm volatile(
        "mma.sync.aligned.m16n8k16.row.col.f32.bf16.bf16.f32 "
        "{%0,%1,%2,%3}, {%4,%5,%6,%7}, {%8,%9}, {%0,%1,%2,%3};"
        : "+f"(c[0]), "+f"(c[1]), "+f"(c[2]), "+f"(c[3])
        : "r"(a[0]), "r"(a[1]), "r"(a[2]), "r"(a[3]), "r"(b[0]), "r"(b[1]));
}

__device__ __forceinline__ uint32_t pack_hilo(float x, float y, uint32_t& lo) {
    __nv_bfloat16 hx = __float2bfloat16(x);
    __nv_bfloat16 hy = __float2bfloat16(y);
    __nv_bfloat16 lx = __float2bfloat16(x - __bfloat162float(hx));
    __nv_bfloat16 ly = __float2bfloat16(y - __bfloat162float(hy));
    lo = (uint32_t)__bfloat16_as_ushort(lx) | ((uint32_t)__bfloat16_as_ushort(ly) << 16);
    return (uint32_t)__bfloat16_as_ushort(hx) | ((uint32_t)__bfloat16_as_ushort(hy) << 16);
}

// ===================== mma.sync GEMM core (128x128, 2 CTA/SM) ================
#define ROW_STRIDE_B 80                 // 32 bf16 (64B) + 16B pad
#define MAT_BYTES (128 * ROW_STRIDE_B)  // 10240
#define STAGE_BYTES (4 * MAT_BYTES)     // 40960
#define GEMM_SMEM (2 * STAGE_BYTES)     // 81920  -> 2 CTAs/SM

__device__ __forceinline__ void load_stage(
    const __nv_bfloat16* a_hi, const __nv_bfloat16* a_lo,
    const __nv_bfloat16* b_hi, const __nv_bfloat16* b_lo,
    int K, int kb, uint32_t sbase, int tid)
{
    const __nv_bfloat16* ptrs[4] = {a_hi, a_lo, b_hi, b_lo};
    #pragma unroll
    for (int i = 0; i < 8; ++i) {
        int idx = tid + i * 256;        // 0..2047
        int mat = idx >> 9;             // 0..3
        int rem = idx & 511;
        int row = rem >> 2;
        int cp  = rem & 3;
        const __nv_bfloat16* src = ptrs[mat] + (size_t)row * K + kb + cp * 8;
        cp16(sbase + mat * MAT_BYTES + row * ROW_STRIDE_B + cp * 16, src);
    }
}

__device__ __forceinline__ void compute_stage(
    uint32_t sbase, int warp_m, int warp_n, int lane, float acc[2][8][4])
{
    const uint32_t ahB = sbase;
    const uint32_t alB = sbase + MAT_BYTES;
    const uint32_t bhB = sbase + 2 * MAT_BYTES;
    const uint32_t blB = sbase + 3 * MAT_BYTES;

    const int lrow = lane & 15;
    const int lk   = (lane >> 4) * 8;
    const int g    = lane >> 3;
    const int nadd = ((g >> 1) << 3) + (lane & 7);
    const int kadd = (g & 1) * 8;

    #pragma unroll
    for (int ks = 0; ks < 2; ++ks) {
        uint32_t ah[2][4], al[2][4];
        #pragma unroll
        for (int mf = 0; mf < 2; ++mf) {
            uint32_t off = (uint32_t)(warp_m * 32 + mf * 16 + lrow) * ROW_STRIDE_B
                         + (ks * 16 + lk) * 2;
            ldm4(ah[mf][0], ah[mf][1], ah[mf][2], ah[mf][3], ahB + off);
            ldm4(al[mf][0], al[mf][1], al[mf][2], al[mf][3], alB + off);
        }
        #pragma unroll
        for (int nf2 = 0; nf2 < 4; ++nf2) {
            uint32_t off = (uint32_t)(warp_n * 64 + nf2 * 16 + nadd) * ROW_STRIDE_B
                         + (ks * 16 + kadd) * 2;
            uint32_t bh[4], bl[4];
            ldm4(bh[0], bh[1], bh[2], bh[3], bhB + off);
            ldm4(bl[0], bl[1], bl[2], bl[3], blB + off);
            #pragma unroll
            for (int mf = 0; mf < 2; ++mf) {
                mma16816(acc[mf][nf2*2],   ah[mf], bh);
                mma16816(acc[mf][nf2*2],   ah[mf], bl);
                mma16816(acc[mf][nf2*2],   al[mf], bh);
                mma16816(acc[mf][nf2*2+1], ah[mf], bh + 2);
                mma16816(acc[mf][nf2*2+1], ah[mf], bl + 2);
                mma16816(acc[mf][nf2*2+1], al[mf], bh + 2);
            }
        }
    }
}

__device__ __forceinline__ void gemm_main(
    const __nv_bfloat16* ahi, const __nv_bfloat16* alo,
    const __nv_bfloat16* bhi, const __nv_bfloat16* blo,
    int K, char* sm, float acc[2][8][4])
{
    const int tid = threadIdx.x;
    const int wid = tid >> 5;
    const int lane = tid & 31;
    const int warp_m = wid & 3;
    const int warp_n = wid >> 2;
    const uint32_t smb = smem_u32(sm);

    #pragma unroll
    for (int mf = 0; mf < 2; ++mf)
        #pragma unroll
        for (int nf = 0; nf < 8; ++nf)
            #pragma unroll
            for (int r = 0; r < 4; ++r) acc[mf][nf][r] = 0.f;

    const int nIters = K / 32;      // 112
    load_stage(ahi, alo, bhi, blo, K, 0, smb, tid);
    CP_COMMIT();
    load_stage(ahi, alo, bhi, blo, K, 32, smb + STAGE_BYTES, tid);
    CP_COMMIT();

    for (int c = 0; c < nIters; ++c) {
        CP_WAIT1();
        __syncthreads();
        compute_stage(smb + (c & 1) * STAGE_BYTES, warp_m, warp_n, lane, acc);
        __syncthreads();
        if (c + 2 < nIters)
            load_stage(ahi, alo, bhi, blo, K, (c + 2) * 32,
                       smb + (c & 1) * STAGE_BYTES, tid);
        CP_COMMIT();
    }
    CP_WAIT0();
}

// ===================== QKV projection =======================================
__global__ __launch_bounds__(256, 2)
void qkv_mma_kernel(const float* __restrict__ bq, const float* __restrict__ bk,
                    const float* __restrict__ bv)
{
    extern __shared__ __align__(128) char sm[];
    const int m0 = blockIdx.x * 128;
    const int n0 = blockIdx.y * 128;

    float acc[2][8][4];
    gemm_main(g_x_hi + (size_t)m0 * HIDDEN,
              g_x_lo + (size_t)m0 * HIDDEN,
              g_w_hi + (size_t)n0 * HIDDEN,
              g_w_lo + (size_t)n0 * HIDDEN,
              HIDDEN, sm, acc);

    float* dst;
    const float* bias;
    if (n0 < N_HEADS * HEAD_DIM) {
        dst = g_q + (size_t)(n0 >> 7) * S_LEN * HEAD_DIM; bias = bq + n0;
    } else if (n0 < (N_HEADS + N_KV) * HEAD_DIM) {
        int o = n0 - N_HEADS * HEAD_DIM;
        dst = g_k + (size_t)(o >> 7) * S_LEN * HEAD_DIM; bias = bk + o;
    } else {
        int o = n0 - (N_HEADS + N_KV) * HEAD_DIM;
        dst = g_v + (size_t)(o >> 7) * S_LEN * HEAD_DIM; bias = bv + o;
    }

    const int tid = threadIdx.x;
    const int wid = tid >> 5;
    const int lane = tid & 31;
    const int warp_m = wid & 3;
    const int warp_n = wid >> 2;

    #pragma unroll
    for (int mf = 0; mf < 2; ++mf) {
        int row = m0 + warp_m * 32 + mf * 16 + (lane >> 2);
        #pragma unroll
        for (int nf = 0; nf < 8; ++nf) {
            int col = warp_n * 64 + nf * 8 + (lane & 3) * 2;   // 0..127
            float b0 = bias[col], b1 = bias[col + 1];
            dst[(size_t)row * HEAD_DIM + col]           = acc[mf][nf][0] + b0;
            dst[(size_t)row * HEAD_DIM + col + 1]       = acc[mf][nf][1] + b1;
            dst[(size_t)(row + 8) * HEAD_DIM + col]     = acc[mf][nf][2] + b0;
            dst[(size_t)(row + 8) * HEAD_DIM + col + 1] = acc[mf][nf][3] + b1;
        }
    }
}

// ===================== output projection ====================================
__global__ __launch_bounds__(256, 2)
void out_mma_kernel(float* __restrict__ out)
{
    extern __shared__ __align__(128) char sm[];
    const int m0 = blockIdx.x * 128;
    const int n0 = blockIdx.y * 128;

    float acc[2][8][4];
    gemm_main(g_at_hi + (size_t)m0 * HIDDEN,
              g_at_lo + (size_t)m0 * HIDDEN,
              g_wo_hi + (size_t)n0 * HIDDEN,
              g_wo_lo + (size_t)n0 * HIDDEN,
              HIDDEN, sm, acc);

    const int tid = threadIdx.x;
    const int wid = tid >> 5;
    const int lane = tid & 31;
    const int warp_m = wid & 3;
    const int warp_n = wid >> 2;

    #pragma unroll
    for (int mf = 0; mf < 2; ++mf) {
        int row = m0 + warp_m * 32 + mf * 16 + (lane >> 2);
        #pragma unroll
        for (int nf = 0; nf < 8; ++nf) {
            int col = n0 + warp_n * 64 + nf * 8 + (lane & 3) * 2;
            out[(size_t)row * HIDDEN + col]           = acc[mf][nf][0];
            out[(size_t)row * HIDDEN + col + 1]       = acc[mf][nf][1];
            out[(size_t)(row + 8) * HIDDEN + col]     = acc[mf][nf][2];
            out[(size_t)(row + 8) * HIDDEN + col + 1] = acc[mf][nf][3];
        }
    }
}

// ===================== fp32 -> bf16 hi/lo split ==============================
__global__ void cvt_split_kernel(const float* __restrict__ src,
                                 __nv_bfloat16* __restrict__ hi,
                                 __nv_bfloat16* __restrict__ lo, int n4)
{
    int i = blockIdx.x * blockDim.x + threadIdx.x;
    if (i >= n4) return;
    float4 v = reinterpret_cast<const float4*>(src)[i];
    __nv_bfloat16 h0 = __float2bfloat16(v.x);
    __nv_bfloat16 h1 = __float2bfloat16(v.y);
    __nv_bfloat16 h2 = __float2bfloat16(v.z);
    __nv_bfloat16 h3 = __float2bfloat16(v.w);
    __nv_bfloat16 l0 = __float2bfloat16(v.x - __bfloat162float(h0));
    __nv_bfloat16 l1 = __float2bfloat16(v.y - __bfloat162float(h1));
    __nv_bfloat16 l2 = __float2bfloat16(v.z - __bfloat162float(h2));
    __nv_bfloat16 l3 = __float2bfloat16(v.w - __bfloat162float(h3));
    ushort4 hv, lv;
    hv.x = __bfloat16_as_ushort(h0); hv.y = __bfloat16_as_ushort(h1);
    hv.z = __bfloat16_as_ushort(h2); hv.w = __bfloat16_as_ushort(h3);
    lv.x = __bfloat16_as_ushort(l0); lv.y = __bfloat16_as_ushort(l1);
    lv.z = __bfloat16_as_ushort(l2); lv.w = __bfloat16_as_ushort(l3);
    reinterpret_cast<ushort4*>(hi)[i] = hv;
    reinterpret_cast<ushort4*>(lo)[i] = lv;
}

// ===================== RoPE + convert to hi/lo bf16 ==========================
__global__ void rope_cvt_kernel(const float* __restrict__ cos_t,
                                const float* __restrict__ sin_t)
{
    int idx = blockIdx.x * blockDim.x + threadIdx.x;
    if (idx >= (N_HEADS + N_KV) * S_LEN * 64) return;
    int d = idx & 63;
    int s = (idx >> 6) & (S_LEN - 1);
    int head = idx >> 17;

    const float* p;
    __nv_bfloat16 *hi, *lo;
    size_t base;
    if (head < N_HEADS) {
        base = (size_t)head * S_LEN * HEAD_DIM;
        p = g_q + base; hi = g_q_hi + base; lo = g_q_lo + base;
    } else {
        base = (size_t)(head - N_HEADS) * S_LEN * HEAD_DIM;
        p = g_k + base; hi = g_k_hi + base; lo = g_k_lo + base;
    }
    float c  = cos_t[s * HEAD_DIM + d];
    float sn = sin_t[s * HEAD_DIM + d];
    float x1 = p[(size_t)s * HEAD_DIM + d];
    float x2 = p[(size_t)s * HEAD_DIM + d + 64];
    float y1 = x1 * c - x2 * sn;
    float y2 = x2 * c + x1 * sn;
    __nv_bfloat16 h1 = __float2bfloat16(y1);
    __nv_bfloat16 h2 = __float2bfloat16(y2);
    size_t o1 = (size_t)s * HEAD_DIM + d;
    size_t o2 = o1 + 64;
    hi[o1] = h1; lo[o1] = __float2bfloat16(y1 - __bfloat162float(h1));
    hi[o2] = h2; lo[o2] = __float2bfloat16(y2 - __bfloat162float(h2));
}

// ===================== V transpose + convert =================================
__global__ void v_cvt_kernel()
{
    int idx = blockIdx.x * blockDim.x + threadIdx.x;
    if (idx >= N_KV * S_LEN * HEAD_DIM) return;
    int kv = idx >> 18;
    int rem = idx & (S_LEN * HEAD_DIM - 1);
    int s = rem >> 7;
    int d = rem & 127;
    float v = g_v[idx];
    __nv_bfloat16 h = __float2bfloat16(v);
    size_t o = (size_t)kv * HEAD_DIM * S_LEN + (size_t)d * S_LEN + s;
    g_vT_hi[o] = h;
    g_vT_lo[o] = __float2bfloat16(v - __bfloat162float(h));
}

// ===================== flash attention (mma.sync, K/V double-buffered) =======
// smem: QH/QL 128x272 = 34816 each; per stage: KH/KL 64x272=17408 each,
// VH/VL 128x144=18432 each (stage 71680). total = 69632 + 2*71680 = 212992.
#define FL_QH 0u
#define FL_QL 34816u
#define FL_ST0 69632u
#define FL_STAGE 71680u
#define FL_KH 0u
#define FL_KL 17408u
#define FL_VH 34816u
#define FL_VL 53248u
#define FLASH_SMEM 212992

__device__ __forceinline__ void flash_load_kv(
    uint32_t sbase, const __nv_bfloat16* kh_g, const __nv_bfloat16* kl_g,
    const __nv_bfloat16* vh_g, const __nv_bfloat16* vl_g, int key0, int tid)
{
    #pragma unroll
    for (int i = 0; i < 4; ++i) {
        int idx = tid + i * 256;
        int row = idx >> 4, cp = idx & 15;
        cp16(sbase + FL_KH + row * 272 + cp * 16,
             kh_g + (size_t)(key0 + row) * HEAD_DIM + cp * 8);
        cp16(sbase + FL_KL + row * 272 + cp * 16,
             kl_g + (size_t)(key0 + row) * HEAD_DIM + cp * 8);
        int vrow = idx >> 3, vcp = idx & 7;
        cp16(sbase + FL_VH + vrow * 144 + vcp * 16,
             vh_g + (size_t)vrow * S_LEN + key0 + vcp * 8);
        cp16(sbase + FL_VL + vrow * 144 + vcp * 16,
             vl_g + (size_t)vrow * S_LEN + key0 + vcp * 8);
    }
}

__global__ __launch_bounds__(256, 1)
void flash_mma_kernel()
{
    extern __shared__ __align__(128) char sm[];
    const uint32_t smb = smem_u32(sm);
    const int qb  = 15 - (int)blockIdx.x;      // big tiles first
    const int h   = blockIdx.y;
    const int kvh = h / GROUPS;
    const int tid = threadIdx.x;
    const int wid = tid >> 5;
    const int lane = tid & 31;
    const int lrow = lane & 15;
    const int lk   = (lane >> 4) * 8;
    const int g    = lane >> 3;
    const int nadd = ((g >> 1) << 3) + (lane & 7);
    const int kadd = (g & 1) * 8;

    const __nv_bfloat16* qh_g = g_q_hi + ((size_t)h * S_LEN + qb * 128) * HEAD_DIM;
    const __nv_bfloat16* ql_g = g_q_lo + ((size_t)h * S_LEN + qb * 128) * HEAD_DIM;
    const __nv_bfloat16* kh_g = g_k_hi + (size_t)kvh * S_LEN * HEAD_DIM;
    const __nv_bfloat16* kl_g = g_k_lo + (size_t)kvh * S_LEN * HEAD_DIM;
    const __nv_bfloat16* vh_g = g_vT_hi + (size_t)kvh * HEAD_DIM * S_LEN;
    const __nv_bfloat16* vl_g = g_vT_lo + (size_t)kvh * HEAD_DIM * S_LEN;

    const int nblk = 2 * qb + 2;   // >= 2 always

    // group 0: Q tile
    #pragma unroll
    for (int i = 0; i < 8; ++i) {
        int idx = tid + i * 256;
        int row = idx >> 4, cp = idx & 15;
        cp16(smb + FL_QH + row * 272 + cp * 16, qh_g + (size_t)row * HEAD_DIM + cp * 8);
        cp16(smb + FL_QL + row * 272 + cp * 16, ql_g + (size_t)row * HEAD_DIM + cp * 8);
    }
    CP_COMMIT();
    // groups 1,2: K/V blocks 0,1
    flash_load_kv(smb + FL_ST0,            kh_g, kl_g, vh_g, vl_g, 0,  tid);
    CP_COMMIT();
    flash_load_kv(smb + FL_ST0 + FL_STAGE, kh_g, kl_g, vh_g, vl_g, 64, tid);
    CP_COMMIT();

    float o[16][4];
    #pragma unroll
    for (int nf = 0; nf < 16; ++nf)
        #pragma unroll
        for (int r = 0; r < 4; ++r) o[nf][r] = 0.f;
    float m0 = -1e30f, m1 = -1e30f, l0 = 0.f, l1 = 0.f;
    const int qr0 = qb * 128 + wid * 16 + (lane >> 2);
    const int qr1 = qr0 + 8;

    for (int blk = 0; blk < nblk; ++blk) {
        const int key0 = blk * 64;
        const uint32_t stg = smb + FL_ST0 + (blk & 1) * FL_STAGE;
        CP_WAIT1();            // Q + K/V(blk) resident
        __syncthreads();

        float s[8][4];
        #pragma unroll
        for (int nf = 0; nf < 8; ++nf)
            #pragma unroll
            for (int r = 0; r < 4; ++r) s[nf][r] = 0.f;

        #pragma unroll
        for (int ks = 0; ks < 8; ++ks) {
            uint32_t qh[4], ql[4];
            uint32_t qoff = (uint32_t)(wid * 16 + lrow) * 272 + (ks * 16 + lk) * 2;
            ldm4(qh[0], qh[1], qh[2], qh[3], smb + FL_QH + qoff);
            ldm4(ql[0], ql[1], ql[2], ql[3], smb + FL_QL + qoff);
            #pragma unroll
            for (int nf2 = 0; nf2 < 4; ++nf2) {
                uint32_t koff = (uint32_t)(nf2 * 16 + nadd) * 272 + (ks * 16 + kadd) * 2;
                uint32_t kh[4], kl[4];
                ldm4(kh[0], kh[1], kh[2], kh[3], stg + FL_KH + koff);
                ldm4(kl[0], kl[1], kl[2], kl[3], stg + FL_KL + koff);
                mma16816(s[nf2*2],   qh, kh);
                mma16816(s[nf2*2],   qh, kl);
                mma16816(s[nf2*2],   ql, kh);
                mma16816(s[nf2*2+1], qh, kh + 2);
                mma16816(s[nf2*2+1], qh, kl + 2);
                mma16816(s[nf2*2+1], ql, kh + 2);
            }
        }

        if (blk >= 2 * qb) {
            #pragma unroll
            for (int nf = 0; nf < 8; ++nf) {
                int c0 = key0 + 8 * nf + 2 * (lane & 3);
                s[nf][0] = (c0     > qr0) ? -1e30f : s[nf][0] * ATTN_SCALE;
                s[nf][1] = (c0 + 1 > qr0) ? -1e30f : s[nf][1] * ATTN_SCALE;
                s[nf][2] = (c0     > qr1) ? -1e30f : s[nf][2] * ATTN_SCALE;
                s[nf][3] = (c0 + 1 > qr1) ? -1e30f : s[nf][3] * ATTN_SCALE;
            }
        } else {
            #pragma unroll
            for (int nf = 0; nf < 8; ++nf)
                #pragma unroll
                for (int r = 0; r < 4; ++r) s[nf][r] *= ATTN_SCALE;
        }

        float mx0 = -1e30f, mx1 = -1e30f;
        #pragma unroll
        for (int nf = 0; nf < 8; ++nf) {
            mx0 = fmaxf(mx0, fmaxf(s[nf][0], s[nf][1]));
            mx1 = fmaxf(mx1, fmaxf(s[nf][2], s[nf][3]));
        }
        mx0 = fmaxf(mx0, __shfl_xor_sync(0xffffffffu, mx0, 1));
        mx0 = fmaxf(mx0, __shfl_xor_sync(0xffffffffu, mx0, 2));
        mx1 = fmaxf(mx1, __shfl_xor_sync(0xffffffffu, mx1, 1));
        mx1 = fmaxf(mx1, __shfl_xor_sync(0xffffffffu, mx1, 2));

        float mn0 = fmaxf(m0, mx0), mn1 = fmaxf(m1, mx1);
        float corr0 = __expf(m0 - mn0), corr1 = __expf(m1 - mn1);
        float sum0 = 0.f, sum1 = 0.f;
        #pragma unroll
        for (int nf = 0; nf < 8; ++nf) {
            s[nf][0] = __expf(s[nf][0] - mn0);
            s[nf][1] = __expf(s[nf][1] - mn0);
            s[nf][2] = __expf(s[nf][2] - mn1);
            s[nf][3] = __expf(s[nf][3] - mn1);
            sum0 += s[nf][0] + s[nf][1];
            sum1 += s[nf][2] + s[nf][3];
        }
        sum0 += __shfl_xor_sync(0xffffffffu, sum0, 1);
        sum0 += __shfl_xor_sync(0xffffffffu, sum0, 2);
        sum1 += __shfl_xor_sync(0xffffffffu, sum1, 1);
        sum1 += __shfl_xor_sync(0xffffffffu, sum1, 2);
        l0 = l0 * corr0 + sum0;  m0 = mn0;
        l1 = l1 * corr1 + sum1;  m1 = mn1;

        #pragma unroll
        for (int nf = 0; nf < 16; ++nf) {
            o[nf][0] *= corr0; o[nf][1] *= corr0;
            o[nf][2] *= corr1; o[nf][3] *= corr1;
        }

        uint32_t ph[4][4], pl[4][4];
        #pragma unroll
        for (int ks = 0; ks < 4; ++ks) {
            int f0 = 2 * ks, f1 = f0 + 1;
            ph[ks][0] = pack_hilo(s[f0][0], s[f0][1], pl[ks][0]);
            ph[ks][1] = pack_hilo(s[f0][2], s[f0][3], pl[ks][1]);
            ph[ks][2] = pack_hilo(s[f1][0], s[f1][1], pl[ks][2]);
            ph[ks][3] = pack_hilo(s[f1][2], s[f1][3], pl[ks][3]);
        }

        #pragma unroll
        for (int ks = 0; ks < 4; ++ks) {
            #pragma unroll
            for (int nf2 = 0; nf2 < 8; ++nf2) {
                uint32_t voff = (uint32_t)(nf2 * 16 + nadd) * 144 + (ks * 16 + kadd) * 2;
                uint32_t vh[4], vl[4];
                ldm4(vh[0], vh[1], vh[2], vh[3], stg + FL_VH + voff);
                ldm4(vl[0], vl[1], vl[2], vl[3], stg + FL_VL + voff);
                mma16816(o[nf2*2],   ph[ks], vh);
                mma16816(o[nf2*2],   pl[ks], vh);
                mma16816(o[nf2*2],   ph[ks], vl);
                mma16816(o[nf2*2+1], ph[ks], vh + 2);
                mma16816(o[nf2*2+1], pl[ks], vh + 2);
                mma16816(o[nf2*2+1], ph[ks], vl + 2);
            }
        }

        // prefetch blk+2 into this stage (reads of this stage are done)
        __syncthreads();
        if (blk + 2 < nblk)
            flash_load_kv(smb + FL_ST0 + (blk & 1) * FL_STAGE,
                          kh_g, kl_g, vh_g, vl_g, (blk + 2) * 64, tid);
        CP_COMMIT();
    }

    float inv0 = 1.f / l0, inv1 = 1.f / l1;
    #pragma unroll
    for (int nf = 0; nf < 16; ++nf) {
        int dcol = 8 * nf + 2 * (lane & 3);
        size_t o0 = (size_t)qr0 * HIDDEN + h * HEAD_DIM + dcol;
        size_t o1 = (size_t)qr1 * HIDDEN + h * HEAD_DIM + dcol;
        uint32_t lo;
        uint32_t hi = pack_hilo(o[nf][0] * inv0, o[nf][1] * inv0, lo);
        *reinterpret_cast<uint32_t*>(g_at_hi + o0) = hi;
        *reinterpret_cast<uint32_t*>(g_at_lo + o0) = lo;
        hi = pack_hilo(o[nf][2] * inv1, o[nf][3] * inv1, lo);
        *reinterpret_cast<uint32_t*>(g_at_hi + o1) = hi;
        *reinterpret_cast<uint32_t*>(g_at_lo + o1) = lo;
    }
}

// ===================== launch ================================================
extern "C" void kernel_launch(void* const* d_in, const int* in_sizes, int n_in,
                              void* d_out, int out_size)
{
    const float* X    = (const float*)d_in[0];
    const float* cosT = (const float*)d_in[1];
    const float* sinT = (const float*)d_in[2];
    const float* Wq   = (const float*)d_in[3];
    const float* bq   = (const float*)d_in[4];
    const float* Wk   = (const float*)d_in[5];
    const float* bk   = (const float*)d_in[6];
    const float* Wv   = (const float*)d_in[7];
    const float* bv   = (const float*)d_in[8];
    const float* Wo   = (const float*)d_in[9];
    float* out = (float*)d_out;

    __nv_bfloat16 *x_hi, *x_lo, *w_hi, *w_lo, *wo_hi, *wo_lo;
    cudaGetSymbolAddress((void**)&x_hi,  g_x_hi);
    cudaGetSymbolAddress((void**)&x_lo,  g_x_lo);
    cudaGetSymbolAddress((void**)&w_hi,  g_w_hi);
    cudaGetSymbolAddress((void**)&w_lo,  g_w_lo);
    cudaGetSymbolAddress((void**)&wo_hi, g_wo_hi);
    cudaGetSymbolAddress((void**)&wo_lo, g_wo_lo);

    cudaFuncSetAttribute(qkv_mma_kernel,  cudaFuncAttributeMaxDynamicSharedMemorySize, GEMM_SMEM);
    cudaFuncSetAttribute(out_mma_kernel,  cudaFuncAttributeMaxDynamicSharedMemorySize, GEMM_SMEM);
    cudaFuncSetAttribute(flash_mma_kernel, cudaFuncAttributeMaxDynamicSharedMemorySize, FLASH_SMEM);

    // 1) convert inputs to bf16 hi/lo
    {
        int n4 = S_LEN * HIDDEN / 4;
        cvt_split_kernel<<<(n4 + 255) / 256, 256>>>(X, x_hi, x_lo, n4);
    }
    {
        int n4 = (N_HEADS * HEAD_DIM) * HIDDEN / 4;
        cvt_split_kernel<<<(n4 + 255) / 256, 256>>>(Wq, w_hi, w_lo, n4);
        int off = N_HEADS * HEAD_DIM * HIDDEN;
        int m4 = (N_KV * HEAD_DIM) * HIDDEN / 4;
        cvt_split_kernel<<<(m4 + 255) / 256, 256>>>(Wk, w_hi + off, w_lo + off, m4);
        off += N_KV * HEAD_DIM * HIDDEN;
        cvt_split_kernel<<<(m4 + 255) / 256, 256>>>(Wv, w_hi + off, w_lo + off, m4);
    }
    {
        int n4 = HIDDEN * HIDDEN / 4;
        cvt_split_kernel<<<(n4 + 255) / 256, 256>>>(Wo, wo_hi, wo_lo, n4);
    }

    // 2) QKV projection (128x128 tiles, 2 CTA/SM)
    qkv_mma_kernel<<<dim3(16, 36), 256, GEMM_SMEM>>>(bq, bk, bv);

    // 3) RoPE -> bf16 hi/lo; V transpose -> bf16 hi/lo
    {
        int n = (N_HEADS + N_KV) * S_LEN * 64;
        rope_cvt_kernel<<<(n + 255) / 256, 256>>>(cosT, sinT);
    }
    {
        int n = N_KV * S_LEN * HEAD_DIM;
        v_cvt_kernel<<<(n + 255) / 256, 256>>>();
    }

    // 4) flash attention (K/V double-buffered)
    flash_mma_kernel<<<dim3(16, N_HEADS), 256, FLASH_SMEM>>>();

    // 5) output projection (128x128 tiles, 2 CTA/SM)
    out_mma_kernel<<<dim3(16, 28), 256, GEMM_SMEM>>>(out);
}